// round 4
// baseline (speedup 1.0000x reference)
#include <cuda_runtime.h>
#include <cuda_bf16.h>
#include <math.h>
#include <stdint.h>

// ---------------------------------------------------------------------------
// ShiftedWindowAttention (B=32, 64x64, C=256, 8 heads x 32, ws=8, shift=4)
//
// GEMMs: mma.sync bf16 (HMMA) with split-bf16 (bf16x3) emulation:
//   x = hi + lo (bf16 each); x*y ~= hiA*hiB + loA*hiB + hiA*loB  (err ~1e-5)
// K0: convert x (gathered) / w_qkv / w_out  -> split bf16 [hi(256)|lo(256)]
// K1: GEMM g_qkv[131072][768] = x2 @ w2^T + b_qkv  (3-stage cp.async pipeline)
// K2: windowed attention (FFMA, float4-vectorized smem), writes split bf16
// K3: GEMM out = att2 @ w3^T + b_out, rows scattered (inverse roll)
// ---------------------------------------------------------------------------

#define KDIM 256
typedef __nv_bfloat16 bf16;

__device__ float g_qkv [131072UL * 768];   // f32 qkv (read by attention)
__device__ bf16  g_x2  [131072UL * 512];   // x gathered, [hi|lo]
__device__ bf16  g_att2[131072UL * 512];   // attention out, [hi|lo]
__device__ bf16  g_w2  [768 * 512];        // w_qkv split
__device__ bf16  g_w3  [256 * 512];        // w_out split

// roll(-4,-4) + window-split source offset for row gm = win*64 + token.
// Same map serves the output scatter (roll(+4,+4) after merge cancels).
__device__ __forceinline__ int gather_off(int gm) {
    int w  = gm >> 6;
    int t  = gm & 63;
    int b  = w >> 6;
    int wl = w & 63;
    int r  = ((wl >> 3) << 3) + (t >> 3);
    int c  = ((wl & 7) << 3) + (t & 7);
    int sr = (r + 4) & 63;
    int sc = (c + 4) & 63;
    return (b * 4096 + sr * 64 + sc) * KDIM;
}

#define SWZ(off) ((off) ^ (((off) >> 3) & 0x70))

__device__ __forceinline__ uint32_t smem_u32(const void* p) {
    uint32_t a;
    asm("{ .reg .u64 t; cvta.to.shared.u64 t, %1; cvt.u32.u64 %0, t; }"
        : "=r"(a) : "l"(p));
    return a;
}

// ---------------------------------------------------------------------------
// K0: split-bf16 conversion. mode 0: x (gathered) -> g_x2
//                            mode 1: w_qkv -> g_w2,  mode 2: w_out -> g_w3
// ---------------------------------------------------------------------------
__global__ void convert_kernel(const float* __restrict__ src, int nrows, int mode)
{
    int idx = blockIdx.x * blockDim.x + threadIdx.x;
    if (idx >= nrows * 64) return;
    int row = idx >> 6;
    int c   = (idx & 63) << 2;
    const float* sp = src + (mode == 0 ? gather_off(row) : row * 256) + c;
    float4 v = *(const float4*)sp;
    bf16* dst = (mode == 0) ? g_x2 : ((mode == 1) ? g_w2 : g_w3);

    float vs[4] = {v.x, v.y, v.z, v.w};
    bf16 __align__(8) hi[4];
    bf16 __align__(8) lo[4];
    #pragma unroll
    for (int i = 0; i < 4; i++) {
        hi[i] = __float2bfloat16(vs[i]);
        lo[i] = __float2bfloat16(vs[i] - __bfloat162float(hi[i]));
    }
    *(uint2*)(dst + (size_t)row * 512 + c)       = *(uint2*)hi;
    *(uint2*)(dst + (size_t)row * 512 + 256 + c) = *(uint2*)lo;
}

// ---------------------------------------------------------------------------
// mma.sync GEMM.  C[128 x 128] per CTA.  8 warps (2 x 4), warp tile 64x32.
// K'' = 768 = 3 segments x 256; K-chunk = 64 bf16 (128 B rows, SW128 swizzle).
// 3-stage cp.async pipeline, one __syncthreads per chunk.
// grid = (NT n-tiles, 1024 m-tiles), n fastest so A tiles share L2.
// ---------------------------------------------------------------------------
template <int NT, bool SCATTER>
__global__ __launch_bounds__(256, 2) void mma_gemm(const float* __restrict__ bias,
                                                   float* __restrict__ Cout)
{
    extern __shared__ __align__(1024) char smem[];
    const bf16* Ag = SCATTER ? g_att2 : g_x2;
    const bf16* Bg = SCATTER ? g_w3   : g_w2;
    float* C = SCATTER ? Cout : g_qkv;
    constexpr int CSTRIDE = NT * 128;

    const int tid  = threadIdx.x;
    const int lane = tid & 31;
    const int warp = tid >> 5;
    const int m0   = blockIdx.y * 128;
    const int n0c  = blockIdx.x * 128;
    const uint32_t sbase = smem_u32(smem);

    // stage chunk c (0..11) into buffer buf. chunk -> gmem cols:
    //   seg = c/4 : 0 -> hiA*hiB, 1 -> loA*hiB, 2 -> hiA*loB
    auto stage = [&](int c, int buf) {
        int seg = c >> 2, kin = (c & 3) * 64;
        int acol = (seg == 1 ? 256 : 0) + kin;
        int bcol = (seg == 2 ? 256 : 0) + kin;
        uint32_t ab = sbase + buf * 32768;
        uint32_t bb = ab + 16384;
        #pragma unroll
        for (int i = 0; i < 4; i++) {
            int idx = tid + i * 256;
            int r  = idx >> 3;
            int ch = idx & 7;
            uint32_t off = (uint32_t)(r * 128 + ch * 16);
            const bf16* as = Ag + (size_t)(m0 + r) * 512 + acol + ch * 8;
            const bf16* bs = Bg + (size_t)(n0c + r) * 512 + bcol + ch * 8;
            asm volatile("cp.async.cg.shared.global [%0], [%1], 16;"
                         :: "r"(ab + SWZ(off)), "l"(as));
            asm volatile("cp.async.cg.shared.global [%0], [%1], 16;"
                         :: "r"(bb + SWZ(off)), "l"(bs));
        }
        asm volatile("cp.async.commit_group;");
    };

    float d[4][4][4];
    #pragma unroll
    for (int mt = 0; mt < 4; mt++)
        #pragma unroll
        for (int nt = 0; nt < 4; nt++)
            #pragma unroll
            for (int j = 0; j < 4; j++) d[mt][nt][j] = 0.f;

    const int wm0 = (warp >> 2) * 64;
    const int wn0 = (warp & 3) * 32;

    stage(0, 0);
    stage(1, 1);
    #pragma unroll 1
    for (int c = 0; c < 12; c++) {
        asm volatile("cp.async.wait_group 1;");
        __syncthreads();
        if (c + 2 < 12) stage(c + 2, (c + 2) % 3);

        uint32_t ab = sbase + (c % 3) * 32768;
        uint32_t bb = ab + 16384;

        #pragma unroll
        for (int ks = 0; ks < 4; ks++) {
            uint32_t a[4][4], b[4][2];
            #pragma unroll
            for (int mt = 0; mt < 4; mt++) {
                int row = wm0 + mt * 16 + (lane & 15);
                int col = ks * 16 + ((lane >> 1) & 8);
                uint32_t off = (uint32_t)(row * 128 + col * 2);
                asm volatile(
                    "ldmatrix.sync.aligned.m8n8.x4.shared.b16 {%0,%1,%2,%3}, [%4];"
                    : "=r"(a[mt][0]), "=r"(a[mt][1]), "=r"(a[mt][2]), "=r"(a[mt][3])
                    : "r"(ab + SWZ(off)));
            }
            #pragma unroll
            for (int np = 0; np < 2; np++) {
                int row = wn0 + np * 16 + (lane & 7) + ((lane & 16) ? 8 : 0);
                int col = ks * 16 + ((lane & 8) ? 8 : 0);
                uint32_t off = (uint32_t)(row * 128 + col * 2);
                asm volatile(
                    "ldmatrix.sync.aligned.m8n8.x4.shared.b16 {%0,%1,%2,%3}, [%4];"
                    : "=r"(b[2 * np][0]), "=r"(b[2 * np][1]),
                      "=r"(b[2 * np + 1][0]), "=r"(b[2 * np + 1][1])
                    : "r"(bb + SWZ(off)));
            }
            #pragma unroll
            for (int mt = 0; mt < 4; mt++)
                #pragma unroll
                for (int nt = 0; nt < 4; nt++)
                    asm volatile(
                        "mma.sync.aligned.m16n8k16.row.col.f32.bf16.bf16.f32 "
                        "{%0,%1,%2,%3}, {%4,%5,%6,%7}, {%8,%9}, {%0,%1,%2,%3};"
                        : "+f"(d[mt][nt][0]), "+f"(d[mt][nt][1]),
                          "+f"(d[mt][nt][2]), "+f"(d[mt][nt][3])
                        : "r"(a[mt][0]), "r"(a[mt][1]), "r"(a[mt][2]), "r"(a[mt][3]),
                          "r"(b[nt][0]), "r"(b[nt][1]));
        }
    }

    // epilogue: bias add + store (row scatter for K3)
    const int cc0 = n0c + wn0 + (lane & 3) * 2;
    #pragma unroll
    for (int mt = 0; mt < 4; mt++) {
        int grow = m0 + wm0 + mt * 16 + (lane >> 2);
        size_t ob0 = SCATTER ? (size_t)gather_off(grow)     : (size_t)grow * CSTRIDE;
        size_t ob1 = SCATTER ? (size_t)gather_off(grow + 8) : (size_t)(grow + 8) * CSTRIDE;
        #pragma unroll
        for (int nt = 0; nt < 4; nt++) {
            int col = cc0 + nt * 8;
            float bx = bias[col], by = bias[col + 1];
            float2 o0 = {d[mt][nt][0] + bx, d[mt][nt][1] + by};
            float2 o1 = {d[mt][nt][2] + bx, d[mt][nt][3] + by};
            *(float2*)(C + ob0 + col) = o0;
            *(float2*)(C + ob1 + col) = o1;
        }
    }
}

// ---------------------------------------------------------------------------
// K2: windowed attention, float4-vectorized smem traffic.
//   qs[i][36]  : q row (scaled), 16B-aligned rows, broadcast float4 reads
//   kT4[d4][64]: k transposed into float4-of-dims, lane-consecutive reads
//   vs[j][33]  : v rows, scalar lane-distinct reads
//   S[i][68]   : probabilities, 16B-aligned rows for broadcast float4 reads
// ---------------------------------------------------------------------------
__global__ __launch_bounds__(128) void attn_kernel(const float* __restrict__ pos_enc)
{
    __shared__ float  qs[64][36];
    __shared__ float4 kT4[8][64];
    __shared__ float  vs[64][33];
    __shared__ float  S[64][68];
    __shared__ float  pe[225];
    __shared__ int    rg[64];

    const int w    = blockIdx.x;
    const int h    = blockIdx.y;
    const int tid  = threadIdx.x;
    const int lane = tid & 31;
    const int warp = tid >> 5;
    const float SCALE = 0.17677669529663687f;

    const float* base = g_qkv + (size_t)w * (64 * 768) + h * 32;
    float* kTf = (float*)kT4;

    for (int idx = tid; idx < 2048; idx += 128) {
        int i = idx >> 5, d = idx & 31;
        qs[i][d] = base[i * 768 + d] * SCALE;
        kTf[((d >> 2) * 64 + i) * 4 + (d & 3)] = base[i * 768 + 256 + d];
        vs[i][d] = base[i * 768 + 512 + d];
    }
    for (int idx = tid; idx < 225; idx += 128) pe[idx] = pos_enc[h * 225 + idx];
    if (tid < 64) {
        int wl = w & 63;
        int r  = ((wl >> 3) << 3) + (tid >> 3);
        int c  = ((wl & 7) << 3) + (tid & 7);
        int rr = (r < 56) ? 0 : ((r < 60) ? 1 : 2);
        int cc = (c < 56) ? 0 : ((c < 60) ? 1 : 2);
        rg[tid] = rr * 3 + cc;
    }
    __syncthreads();

    for (int i0 = warp * 16; i0 < warp * 16 + 16; i0 += 4) {
        float a0[4] = {0, 0, 0, 0}, a1[4] = {0, 0, 0, 0};
        #pragma unroll
        for (int d4 = 0; d4 < 8; d4++) {
            float4 k0 = kT4[d4][lane];
            float4 k1 = kT4[d4][lane + 32];
            #pragma unroll
            for (int r = 0; r < 4; r++) {
                float4 qv = *(const float4*)&qs[i0 + r][d4 * 4];
                a0[r] += qv.x * k0.x + qv.y * k0.y + qv.z * k0.z + qv.w * k0.w;
                a1[r] += qv.x * k1.x + qv.y * k1.y + qv.z * k1.z + qv.w * k1.w;
            }
        }
        #pragma unroll
        for (int r = 0; r < 4; r++) {
            int i = i0 + r;
            int yi = i >> 3, xi = i & 7, ri = rg[i];
            int j0 = lane, j1 = lane + 32;
            float s0 = a0[r] + pe[(yi - (j0 >> 3) + 7) * 15 + (xi - (j0 & 7) + 7)];
            float s1 = a1[r] + pe[(yi - (j1 >> 3) + 7) * 15 + (xi - (j1 & 7) + 7)];
            if (rg[j0] != ri) s0 = -INFINITY;
            if (rg[j1] != ri) s1 = -INFINITY;
            float mx = fmaxf(s0, s1);
            #pragma unroll
            for (int o = 16; o > 0; o >>= 1) mx = fmaxf(mx, __shfl_xor_sync(0xffffffffu, mx, o));
            float e0 = __expf(s0 - mx);
            float e1 = __expf(s1 - mx);
            float sm = e0 + e1;
            #pragma unroll
            for (int o = 16; o > 0; o >>= 1) sm += __shfl_xor_sync(0xffffffffu, sm, o);
            float inv = 1.0f / sm;
            S[i][j0] = e0 * inv;
            S[i][j1] = e1 * inv;
        }
    }
    __syncthreads();

    // O = S v, write split bf16 to g_att2
    size_t obase = (size_t)(w * 64) * 512 + h * 32 + lane;
    for (int i0 = warp * 16; i0 < warp * 16 + 16; i0 += 4) {
        float acc[4] = {0, 0, 0, 0};
        #pragma unroll
        for (int j4 = 0; j4 < 16; j4++) {
            float v0 = vs[j4 * 4 + 0][lane];
            float v1 = vs[j4 * 4 + 1][lane];
            float v2 = vs[j4 * 4 + 2][lane];
            float v3 = vs[j4 * 4 + 3][lane];
            #pragma unroll
            for (int r = 0; r < 4; r++) {
                float4 s = *(const float4*)&S[i0 + r][j4 * 4];
                acc[r] += s.x * v0 + s.y * v1 + s.z * v2 + s.w * v3;
            }
        }
        #pragma unroll
        for (int r = 0; r < 4; r++) {
            float vacc = acc[r];
            bf16 hb = __float2bfloat16(vacc);
            bf16 lb = __float2bfloat16(vacc - __bfloat162float(hb));
            size_t ro = obase + (size_t)(i0 + r) * 512;
            g_att2[ro]       = hb;
            g_att2[ro + 256] = lb;
        }
    }
}

// ---------------------------------------------------------------------------
extern "C" void kernel_launch(void* const* d_in, const int* in_sizes, int n_in,
                              void* d_out, int out_size)
{
    const float* x     = (const float*)d_in[0];
    const float* w_qkv = (const float*)d_in[1];
    const float* b_qkv = (const float*)d_in[2];
    const float* w_out = (const float*)d_in[3];
    const float* b_out = (const float*)d_in[4];
    const float* pos   = (const float*)d_in[5];
    float* out = (float*)d_out;

    const int SMEM = 98304;   // 3 x (16KB A + 16KB B)
    cudaFuncSetAttribute(mma_gemm<6, false>,
                         cudaFuncAttributeMaxDynamicSharedMemorySize, SMEM);
    cudaFuncSetAttribute(mma_gemm<2, true>,
                         cudaFuncAttributeMaxDynamicSharedMemorySize, SMEM);

    // K0: conversions
    convert_kernel<<<32768, 256>>>(x, 131072, 0);
    convert_kernel<<<192,   256>>>(w_qkv, 768, 1);
    convert_kernel<<<64,    256>>>(w_out, 256, 2);
    // K1: QKV projection (HMMA, bf16x3)
    mma_gemm<6, false><<<dim3(6, 1024), 256, SMEM>>>(b_qkv, nullptr);
    // K2: windowed attention
    attn_kernel<<<dim3(2048, 8), 128>>>(pos);
    // K3: output projection + scatter (HMMA, bf16x3)
    mma_gemm<2, true><<<dim3(2, 1024), 256, SMEM>>>(b_out, out);
}

// round 5
// speedup vs baseline: 2.0430x; 2.0430x over previous
#include <cuda_runtime.h>
#include <cuda_bf16.h>
#include <math.h>
#include <stdint.h>

// ---------------------------------------------------------------------------
// ShiftedWindowAttention (B=32, 64x64, C=256, 8 heads x 32, ws=8, shift=4)
//
// All matmuls on HMMA (mma.sync bf16) with split-bf16 emulation:
//   x = hi + lo (bf16); x*y ~= hiA*hiB + loA*hiB + hiA*loB
// K0: convert x (gathered) / w_qkv / w_out  -> split bf16 [hi(256)|lo(256)]
// K1: GEMM g_qkv[131072][768] = x2 @ w2^T + b_qkv   (R3 2-stage pipeline)
// K2: windowed attention, fully tensor-core (QK^T and P.V on mma.sync,
//     register-resident S, softmax on fragments), writes split bf16
// K3: GEMM out = att2 @ w3^T + b_out, rows scattered (inverse roll)
// ---------------------------------------------------------------------------

#define KDIM 256
typedef __nv_bfloat16 bf16;

__device__ float g_qkv [131072UL * 768];
__device__ bf16  g_x2  [131072UL * 512];
__device__ bf16  g_att2[131072UL * 512];
__device__ bf16  g_w2  [768 * 512];
__device__ bf16  g_w3  [256 * 512];

__device__ __forceinline__ int gather_off(int gm) {
    int w  = gm >> 6;
    int t  = gm & 63;
    int b  = w >> 6;
    int wl = w & 63;
    int r  = ((wl >> 3) << 3) + (t >> 3);
    int c  = ((wl & 7) << 3) + (t & 7);
    int sr = (r + 4) & 63;
    int sc = (c + 4) & 63;
    return (b * 4096 + sr * 64 + sc) * KDIM;
}

#define SWZ(off) ((off) ^ (((off) >> 3) & 0x70))

__device__ __forceinline__ uint32_t smem_u32(const void* p) {
    uint32_t a;
    asm("{ .reg .u64 t; cvta.to.shared.u64 t, %1; cvt.u32.u64 %0, t; }"
        : "=r"(a) : "l"(p));
    return a;
}

#define LDSM4(r, addr)                                                         \
    asm volatile("ldmatrix.sync.aligned.m8n8.x4.shared.b16 {%0,%1,%2,%3}, [%4];"\
                 : "=r"((r)[0]), "=r"((r)[1]), "=r"((r)[2]), "=r"((r)[3])      \
                 : "r"(addr))

#define MMA16816(d, a, b)                                                      \
    asm volatile("mma.sync.aligned.m16n8k16.row.col.f32.bf16.bf16.f32 "        \
                 "{%0,%1,%2,%3}, {%4,%5,%6,%7}, {%8,%9}, {%0,%1,%2,%3};"       \
                 : "+f"((d)[0]), "+f"((d)[1]), "+f"((d)[2]), "+f"((d)[3])      \
                 : "r"((a)[0]), "r"((a)[1]), "r"((a)[2]), "r"((a)[3]),         \
                   "r"((b)[0]), "r"((b)[1]))

__device__ __forceinline__ uint32_t packbf(float lo, float hi) {
    uint32_t r;
    asm("cvt.rn.bf16x2.f32 %0, %1, %2;" : "=r"(r) : "f"(hi), "f"(lo));
    return r;
}
__device__ __forceinline__ float bfhi(float x) {
    return __bfloat162float(__float2bfloat16(x));
}

// ---------------------------------------------------------------------------
// K0: split-bf16 conversion
// ---------------------------------------------------------------------------
__global__ void convert_kernel(const float* __restrict__ src, int nrows, int mode)
{
    int idx = blockIdx.x * blockDim.x + threadIdx.x;
    if (idx >= nrows * 64) return;
    int row = idx >> 6;
    int c   = (idx & 63) << 2;
    const float* sp = src + (mode == 0 ? gather_off(row) : row * 256) + c;
    float4 v = *(const float4*)sp;
    bf16* dst = (mode == 0) ? g_x2 : ((mode == 1) ? g_w2 : g_w3);

    float vs[4] = {v.x, v.y, v.z, v.w};
    bf16 __align__(8) hi[4];
    bf16 __align__(8) lo[4];
    #pragma unroll
    for (int i = 0; i < 4; i++) {
        hi[i] = __float2bfloat16(vs[i]);
        lo[i] = __float2bfloat16(vs[i] - __bfloat162float(hi[i]));
    }
    *(uint2*)(dst + (size_t)row * 512 + c)       = *(uint2*)hi;
    *(uint2*)(dst + (size_t)row * 512 + 256 + c) = *(uint2*)lo;
}

// ---------------------------------------------------------------------------
// mma.sync GEMM (identical to the round-3 version that measured 400us on K1)
// ---------------------------------------------------------------------------
template <int NT, bool SCATTER>
__global__ __launch_bounds__(256, 2) void mma_gemm(const float* __restrict__ bias,
                                                   float* __restrict__ Cout)
{
    extern __shared__ __align__(1024) char smem[];
    const bf16* Ag = SCATTER ? g_att2 : g_x2;
    const bf16* Bg = SCATTER ? g_w3   : g_w2;
    float* C = SCATTER ? Cout : g_qkv;
    constexpr int CSTRIDE = NT * 128;

    const int tid  = threadIdx.x;
    const int lane = tid & 31;
    const int warp = tid >> 5;
    const int m0   = blockIdx.y * 128;
    const int n0c  = blockIdx.x * 128;
    const uint32_t sbase = smem_u32(smem);

    auto stage = [&](int c, int buf) {
        int seg = c >> 2, kin = (c & 3) * 64;
        int acol = (seg == 1 ? 256 : 0) + kin;
        int bcol = (seg == 2 ? 256 : 0) + kin;
        uint32_t ab = sbase + buf * 32768;
        uint32_t bb = ab + 16384;
        #pragma unroll
        for (int i = 0; i < 4; i++) {
            int idx = tid + i * 256;
            int r  = idx >> 3;
            int ch = idx & 7;
            uint32_t off = (uint32_t)(r * 128 + ch * 16);
            const bf16* as = Ag + (size_t)(m0 + r) * 512 + acol + ch * 8;
            const bf16* bs = Bg + (size_t)(n0c + r) * 512 + bcol + ch * 8;
            asm volatile("cp.async.cg.shared.global [%0], [%1], 16;"
                         :: "r"(ab + SWZ(off)), "l"(as));
            asm volatile("cp.async.cg.shared.global [%0], [%1], 16;"
                         :: "r"(bb + SWZ(off)), "l"(bs));
        }
        asm volatile("cp.async.commit_group;");
    };

    float d[4][4][4];
    #pragma unroll
    for (int mt = 0; mt < 4; mt++)
        #pragma unroll
        for (int nt = 0; nt < 4; nt++)
            #pragma unroll
            for (int j = 0; j < 4; j++) d[mt][nt][j] = 0.f;

    const int wm0 = (warp >> 2) * 64;
    const int wn0 = (warp & 3) * 32;

    stage(0, 0);
    for (int c = 0; c < 12; c++) {
        if (c < 11) {
            stage(c + 1, (c + 1) & 1);
            asm volatile("cp.async.wait_group 1;");
        } else {
            asm volatile("cp.async.wait_group 0;");
        }
        __syncthreads();

        uint32_t ab = sbase + (c & 1) * 32768;
        uint32_t bb = ab + 16384;

        #pragma unroll
        for (int ks = 0; ks < 4; ks++) {
            uint32_t a[4][4], b[4][2];
            #pragma unroll
            for (int mt = 0; mt < 4; mt++) {
                int row = wm0 + mt * 16 + (lane & 15);
                int col = ks * 16 + ((lane >> 1) & 8);
                uint32_t off = (uint32_t)(row * 128 + col * 2);
                LDSM4(a[mt], ab + SWZ(off));
            }
            #pragma unroll
            for (int np = 0; np < 2; np++) {
                int row = wn0 + np * 16 + (lane & 7) + ((lane & 16) ? 8 : 0);
                int col = ks * 16 + ((lane & 8) ? 8 : 0);
                uint32_t off = (uint32_t)(row * 128 + col * 2);
                uint32_t t[4];
                LDSM4(t, bb + SWZ(off));
                b[2 * np][0] = t[0]; b[2 * np][1] = t[1];
                b[2 * np + 1][0] = t[2]; b[2 * np + 1][1] = t[3];
            }
            #pragma unroll
            for (int mt = 0; mt < 4; mt++)
                #pragma unroll
                for (int nt = 0; nt < 4; nt++)
                    MMA16816(d[mt][nt], a[mt], b[nt]);
        }
        if (c < 11) __syncthreads();
    }

    const int cc0 = n0c + wn0 + (lane & 3) * 2;
    #pragma unroll
    for (int mt = 0; mt < 4; mt++) {
        int grow = m0 + wm0 + mt * 16 + (lane >> 2);
        size_t ob0 = SCATTER ? (size_t)gather_off(grow)     : (size_t)grow * CSTRIDE;
        size_t ob1 = SCATTER ? (size_t)gather_off(grow + 8) : (size_t)(grow + 8) * CSTRIDE;
        #pragma unroll
        for (int nt = 0; nt < 4; nt++) {
            int col = cc0 + nt * 8;
            float bx = bias[col], by = bias[col + 1];
            float2 o0 = {d[mt][nt][0] + bx, d[mt][nt][1] + by};
            float2 o1 = {d[mt][nt][2] + bx, d[mt][nt][3] + by};
            *(float2*)(C + ob0 + col) = o0;
            *(float2*)(C + ob1 + col) = o1;
        }
    }
}

// ---------------------------------------------------------------------------
// K2: tensor-core windowed attention. One block per (window, head), 4 warps,
// warp owns 16 query rows. S register-resident; softmax on fragments
// (row lives on 4 lanes -> 2 shuffles). P repacked C-frag -> A-frag, split
// hi/lo bf16. QK^T and P.V each 3 split-segments on mma.sync.
// ---------------------------------------------------------------------------
__global__ __launch_bounds__(128) void attn_kernel(const float* __restrict__ pos_enc)
{
    __shared__ bf16 qh[64 * 40], ql[64 * 40];
    __shared__ bf16 kh[64 * 40], kl[64 * 40];
    __shared__ bf16 vh[32 * 72], vl[32 * 72];   // transposed [dim][col]
    __shared__ float pe[225];
    __shared__ int   rg[64];

    const int w    = blockIdx.x;
    const int h    = blockIdx.y;
    const int tid  = threadIdx.x;
    const int lane = tid & 31;
    const int wp   = tid >> 5;
    const float SCALE = 0.17677669529663687f;

    const float* base = g_qkv + (size_t)w * (64 * 768) + h * 32;

    // load + split q,k,v
    for (int idx = tid; idx < 2048; idx += 128) {
        int i = idx >> 5, d = idx & 31;
        float qf = base[i * 768 + d] * SCALE;
        bf16 qb = __float2bfloat16(qf);
        qh[i * 40 + d] = qb;
        ql[i * 40 + d] = __float2bfloat16(qf - __bfloat162float(qb));
        float kf = base[i * 768 + 256 + d];
        bf16 kb = __float2bfloat16(kf);
        kh[i * 40 + d] = kb;
        kl[i * 40 + d] = __float2bfloat16(kf - __bfloat162float(kb));
        float vf = base[i * 768 + 512 + d];
        bf16 vb = __float2bfloat16(vf);
        vh[d * 72 + i] = vb;
        vl[d * 72 + i] = __float2bfloat16(vf - __bfloat162float(vb));
    }
    for (int idx = tid; idx < 225; idx += 128) pe[idx] = pos_enc[h * 225 + idx];
    if (tid < 64) {
        int wl = w & 63;
        int r  = ((wl >> 3) << 3) + (tid >> 3);
        int c  = ((wl & 7) << 3) + (tid & 7);
        int rr = (r < 56) ? 0 : ((r < 60) ? 1 : 2);
        int cc = (c < 56) ? 0 : ((c < 60) ? 1 : 2);
        rg[tid] = rr * 3 + cc;
    }
    __syncthreads();

    const uint32_t uqh = smem_u32(qh), uql = smem_u32(ql);
    const uint32_t ukh = smem_u32(kh), ukl = smem_u32(kl);
    const uint32_t uvh = smem_u32(vh), uvl = smem_u32(vl);

    // ---- S = q k^T (3 segments), c[ntile][4] ----
    float c[8][4];
    #pragma unroll
    for (int j = 0; j < 8; j++)
        #pragma unroll
        for (int q = 0; q < 4; q++) c[j][q] = 0.f;

    uint32_t aqh[2][4], aql[2][4];
    #pragma unroll
    for (int ks = 0; ks < 2; ks++) {
        uint32_t off = (uint32_t)((wp * 16 + (lane & 15)) * 80 +
                                  (ks * 16 + ((lane >> 1) & 8)) * 2);
        LDSM4(aqh[ks], uqh + off);
        LDSM4(aql[ks], uql + off);
    }
    #pragma unroll
    for (int np = 0; np < 4; np++) {
        #pragma unroll
        for (int ks = 0; ks < 2; ks++) {
            uint32_t off = (uint32_t)((np * 16 + (lane & 7) + ((lane & 16) ? 8 : 0)) * 80 +
                                      (ks * 16 + ((lane & 8) ? 8 : 0)) * 2);
            uint32_t bh[4], bl[4];
            LDSM4(bh, ukh + off);
            LDSM4(bl, ukl + off);
            #pragma unroll
            for (int n2 = 0; n2 < 2; n2++) {
                MMA16816(c[2 * np + n2], aqh[ks], &bh[2 * n2]);
                MMA16816(c[2 * np + n2], aql[ks], &bh[2 * n2]);
                MMA16816(c[2 * np + n2], aqh[ks], &bl[2 * n2]);
            }
        }
    }

    // ---- bias + mask + softmax on fragments ----
    const int r0 = wp * 16 + (lane >> 2);
    const int r1 = r0 + 8;
    const int yi0 = r0 >> 3, xi0 = r0 & 7, ri0 = rg[r0];
    const int yi1 = r1 >> 3, xi1 = r1 & 7, ri1 = rg[r1];
    float mx0 = -INFINITY, mx1 = -INFINITY;
    #pragma unroll
    for (int j = 0; j < 8; j++) {
        #pragma unroll
        for (int dd = 0; dd < 2; dd++) {
            int col = j * 8 + (lane & 3) * 2 + dd;
            int yj = col >> 3, xj = col & 7;
            int rc = rg[col];
            c[j][dd]     = (rc == ri0)
                ? c[j][dd]     + pe[(yi0 - yj + 7) * 15 + (xi0 - xj + 7)] : -INFINITY;
            c[j][dd + 2] = (rc == ri1)
                ? c[j][dd + 2] + pe[(yi1 - yj + 7) * 15 + (xi1 - xj + 7)] : -INFINITY;
            mx0 = fmaxf(mx0, c[j][dd]);
            mx1 = fmaxf(mx1, c[j][dd + 2]);
        }
    }
    mx0 = fmaxf(mx0, __shfl_xor_sync(0xffffffffu, mx0, 1));
    mx0 = fmaxf(mx0, __shfl_xor_sync(0xffffffffu, mx0, 2));
    mx1 = fmaxf(mx1, __shfl_xor_sync(0xffffffffu, mx1, 1));
    mx1 = fmaxf(mx1, __shfl_xor_sync(0xffffffffu, mx1, 2));
    float s0 = 0.f, s1 = 0.f;
    #pragma unroll
    for (int j = 0; j < 8; j++) {
        #pragma unroll
        for (int dd = 0; dd < 2; dd++) {
            c[j][dd]     = __expf(c[j][dd] - mx0);     s0 += c[j][dd];
            c[j][dd + 2] = __expf(c[j][dd + 2] - mx1); s1 += c[j][dd + 2];
        }
    }
    s0 += __shfl_xor_sync(0xffffffffu, s0, 1);
    s0 += __shfl_xor_sync(0xffffffffu, s0, 2);
    s1 += __shfl_xor_sync(0xffffffffu, s1, 1);
    s1 += __shfl_xor_sync(0xffffffffu, s1, 2);
    const float inv0 = 1.0f / s0, inv1 = 1.0f / s1;
    #pragma unroll
    for (int j = 0; j < 8; j++) {
        c[j][0] *= inv0; c[j][1] *= inv0;
        c[j][2] *= inv1; c[j][3] *= inv1;
    }

    // ---- repack P (C-frag -> A-frag), split hi/lo ----
    uint32_t ph[4][4], pl[4][4];
    #pragma unroll
    for (int t = 0; t < 4; t++) {
        #pragma unroll
        for (int q = 0; q < 4; q++) {
            int nt = 2 * t + (q >> 1);
            int p0 = (q & 1) * 2;
            float x0 = c[nt][p0], x1 = c[nt][p0 + 1];
            float h0 = bfhi(x0), h1 = bfhi(x1);
            ph[t][q] = packbf(h0, h1);
            pl[t][q] = packbf(x0 - h0, x1 - h1);
        }
    }

    // ---- O = P v (3 segments) ----
    float o[4][4];
    #pragma unroll
    for (int nt = 0; nt < 4; nt++)
        #pragma unroll
        for (int q = 0; q < 4; q++) o[nt][q] = 0.f;

    #pragma unroll
    for (int t = 0; t < 4; t++) {
        #pragma unroll
        for (int nb = 0; nb < 2; nb++) {
            uint32_t off = (uint32_t)((nb * 16 + (lane & 7) + ((lane & 16) ? 8 : 0)) * 144 +
                                      (t * 16 + ((lane & 8) ? 8 : 0)) * 2);
            uint32_t bh[4], bl[4];
            LDSM4(bh, uvh + off);
            LDSM4(bl, uvl + off);
            #pragma unroll
            for (int n2 = 0; n2 < 2; n2++) {
                MMA16816(o[2 * nb + n2], ph[t], &bh[2 * n2]);
                MMA16816(o[2 * nb + n2], pl[t], &bh[2 * n2]);
                MMA16816(o[2 * nb + n2], ph[t], &bl[2 * n2]);
            }
        }
    }

    // ---- epilogue: split bf16 to g_att2 ----
    size_t rb0 = (size_t)(w * 64 + r0) * 512 + h * 32;
    size_t rb1 = (size_t)(w * 64 + r1) * 512 + h * 32;
    #pragma unroll
    for (int nt = 0; nt < 4; nt++) {
        int d0 = nt * 8 + (lane & 3) * 2;
        float a0 = o[nt][0], a1 = o[nt][1], a2 = o[nt][2], a3 = o[nt][3];
        float h0 = bfhi(a0), h1 = bfhi(a1), h2 = bfhi(a2), h3 = bfhi(a3);
        *(uint32_t*)(g_att2 + rb0 + d0)       = packbf(h0, h1);
        *(uint32_t*)(g_att2 + rb0 + 256 + d0) = packbf(a0 - h0, a1 - h1);
        *(uint32_t*)(g_att2 + rb1 + d0)       = packbf(h2, h3);
        *(uint32_t*)(g_att2 + rb1 + 256 + d0) = packbf(a2 - h2, a3 - h3);
    }
}

// ---------------------------------------------------------------------------
extern "C" void kernel_launch(void* const* d_in, const int* in_sizes, int n_in,
                              void* d_out, int out_size)
{
    const float* x     = (const float*)d_in[0];
    const float* w_qkv = (const float*)d_in[1];
    const float* b_qkv = (const float*)d_in[2];
    const float* w_out = (const float*)d_in[3];
    const float* b_out = (const float*)d_in[4];
    const float* pos   = (const float*)d_in[5];
    float* out = (float*)d_out;

    const int SMEM = 65536;
    cudaFuncSetAttribute(mma_gemm<6, false>,
                         cudaFuncAttributeMaxDynamicSharedMemorySize, SMEM);
    cudaFuncSetAttribute(mma_gemm<2, true>,
                         cudaFuncAttributeMaxDynamicSharedMemorySize, SMEM);

    convert_kernel<<<32768, 256>>>(x, 131072, 0);
    convert_kernel<<<192,   256>>>(w_qkv, 768, 1);
    convert_kernel<<<64,    256>>>(w_out, 256, 2);
    mma_gemm<6, false><<<dim3(6, 1024), 256, SMEM>>>(b_qkv, nullptr);
    attn_kernel<<<dim3(2048, 8), 128>>>(pos);
    mma_gemm<2, true><<<dim3(2, 1024), 256, SMEM>>>(b_out, out);
}

// round 6
// speedup vs baseline: 2.5611x; 1.2536x over previous
#include <cuda_runtime.h>
#include <cuda_fp16.h>
#include <math.h>
#include <stdint.h>

// ---------------------------------------------------------------------------
// ShiftedWindowAttention (B=32, 64x64, C=256, 8 heads x 32, ws=8, shift=4)
//
// All matmuls on HMMA (mma.sync fp16, fp32 accum) with 2-segment split:
//   A = ah + al (fp16); B ~= bh (fp16)  =>  C = ah*bh + al*bh   (err ~2^-12)
// K0: convert x (gathered) -> [hi|lo] fp16; w_qkv / w_out -> hi fp16
// K1: GEMM g_qkv[131072][768] = x2 @ w2h^T + b_qkv   (8 chunk pipeline)
// K2: windowed attention, tensor-core (q split, k hi; P split, v hi)
// K3: GEMM out = att2 @ w3h^T + b_out, rows scattered (inverse roll)
// ---------------------------------------------------------------------------

#define KDIM 256
typedef __half fp16;

__device__ float g_qkv [131072UL * 768];
__device__ fp16  g_x2  [131072UL * 512];   // x gathered, [hi(256)|lo(256)]
__device__ fp16  g_att2[131072UL * 512];   // attention out, [hi|lo]
__device__ fp16  g_w2  [768 * 256];        // w_qkv hi
__device__ fp16  g_w3  [256 * 256];        // w_out hi

__device__ __forceinline__ int gather_off(int gm) {
    int w  = gm >> 6;
    int t  = gm & 63;
    int b  = w >> 6;
    int wl = w & 63;
    int r  = ((wl >> 3) << 3) + (t >> 3);
    int c  = ((wl & 7) << 3) + (t & 7);
    int sr = (r + 4) & 63;
    int sc = (c + 4) & 63;
    return (b * 4096 + sr * 64 + sc) * KDIM;
}

#define SWZ(off) ((off) ^ (((off) >> 3) & 0x70))

__device__ __forceinline__ uint32_t smem_u32(const void* p) {
    uint32_t a;
    asm("{ .reg .u64 t; cvta.to.shared.u64 t, %1; cvt.u32.u64 %0, t; }"
        : "=r"(a) : "l"(p));
    return a;
}

#define LDSM4(r, addr)                                                         \
    asm volatile("ldmatrix.sync.aligned.m8n8.x4.shared.b16 {%0,%1,%2,%3}, [%4];"\
                 : "=r"((r)[0]), "=r"((r)[1]), "=r"((r)[2]), "=r"((r)[3])      \
                 : "r"(addr))

#define MMA16816(d, a, b)                                                      \
    asm volatile("mma.sync.aligned.m16n8k16.row.col.f32.f16.f16.f32 "          \
                 "{%0,%1,%2,%3}, {%4,%5,%6,%7}, {%8,%9}, {%0,%1,%2,%3};"       \
                 : "+f"((d)[0]), "+f"((d)[1]), "+f"((d)[2]), "+f"((d)[3])      \
                 : "r"((a)[0]), "r"((a)[1]), "r"((a)[2]), "r"((a)[3]),         \
                   "r"((b)[0]), "r"((b)[1]))

__device__ __forceinline__ uint32_t packh(float lo, float hi) {
    __half2 h = __floats2half2_rn(lo, hi);
    return *(uint32_t*)&h;
}
__device__ __forceinline__ float fhhi(float x) {
    return __half2float(__float2half_rn(x));
}

// ---------------------------------------------------------------------------
// K0: conversion. mode 0: x (gathered) -> g_x2 [hi|lo]
//                 mode 1: w_qkv -> g_w2 hi,  mode 2: w_out -> g_w3 hi
// ---------------------------------------------------------------------------
__global__ void convert_kernel(const float* __restrict__ src, int nrows, int mode)
{
    int idx = blockIdx.x * blockDim.x + threadIdx.x;
    if (idx >= nrows * 64) return;
    int row = idx >> 6;
    int c   = (idx & 63) << 2;
    const float* sp = src + (mode == 0 ? gather_off(row) : row * 256) + c;
    float4 v = *(const float4*)sp;

    float vs[4] = {v.x, v.y, v.z, v.w};
    fp16 __align__(8) hi[4];
    #pragma unroll
    for (int i = 0; i < 4; i++) hi[i] = __float2half_rn(vs[i]);

    if (mode == 0) {
        fp16 __align__(8) lo[4];
        #pragma unroll
        for (int i = 0; i < 4; i++)
            lo[i] = __float2half_rn(vs[i] - __half2float(hi[i]));
        *(uint2*)(g_x2 + (size_t)row * 512 + c)       = *(uint2*)hi;
        *(uint2*)(g_x2 + (size_t)row * 512 + 256 + c) = *(uint2*)lo;
    } else {
        fp16* dst = (mode == 1) ? g_w2 : g_w3;
        *(uint2*)(dst + (size_t)row * 256 + c) = *(uint2*)hi;
    }
}

// ---------------------------------------------------------------------------
// mma.sync GEMM.  C[128 x 128] per CTA, 8 warps, warp tile 64x32.
// K'' = 512 = 2 segments x 256 (A: hi then lo; B: hi both);
// chunk = 64 cols, 2-stage cp.async pipeline (round-3 structure).
// ---------------------------------------------------------------------------
template <int NT, bool SCATTER>
__global__ __launch_bounds__(256, 2) void mma_gemm(const float* __restrict__ bias,
                                                   float* __restrict__ Cout)
{
    extern __shared__ __align__(1024) char smem[];
    const fp16* Ag = SCATTER ? g_att2 : g_x2;
    const fp16* Bg = SCATTER ? g_w3   : g_w2;
    float* C = SCATTER ? Cout : g_qkv;
    constexpr int CSTRIDE = NT * 128;

    const int tid  = threadIdx.x;
    const int lane = tid & 31;
    const int warp = tid >> 5;
    const int m0   = blockIdx.y * 128;
    const int n0c  = blockIdx.x * 128;
    const uint32_t sbase = smem_u32(smem);

    // chunk c (0..7): A cols = (c>>2)*256 + (c&3)*64 ; B cols = (c&3)*64
    auto stage = [&](int c, int buf) {
        int kin  = (c & 3) * 64;
        int acol = (c >> 2) * 256 + kin;
        uint32_t ab = sbase + buf * 32768;
        uint32_t bb = ab + 16384;
        #pragma unroll
        for (int i = 0; i < 4; i++) {
            int idx = tid + i * 256;
            int r  = idx >> 3;
            int ch = idx & 7;
            uint32_t off = (uint32_t)(r * 128 + ch * 16);
            const fp16* as = Ag + (size_t)(m0 + r) * 512 + acol + ch * 8;
            const fp16* bs = Bg + (size_t)(n0c + r) * 256 + kin + ch * 8;
            asm volatile("cp.async.cg.shared.global [%0], [%1], 16;"
                         :: "r"(ab + SWZ(off)), "l"(as));
            asm volatile("cp.async.cg.shared.global [%0], [%1], 16;"
                         :: "r"(bb + SWZ(off)), "l"(bs));
        }
        asm volatile("cp.async.commit_group;");
    };

    float d[4][4][4];
    #pragma unroll
    for (int mt = 0; mt < 4; mt++)
        #pragma unroll
        for (int nt = 0; nt < 4; nt++)
            #pragma unroll
            for (int j = 0; j < 4; j++) d[mt][nt][j] = 0.f;

    const int wm0 = (warp >> 2) * 64;
    const int wn0 = (warp & 3) * 32;

    stage(0, 0);
    for (int c = 0; c < 8; c++) {
        if (c < 7) {
            stage(c + 1, (c + 1) & 1);
            asm volatile("cp.async.wait_group 1;");
        } else {
            asm volatile("cp.async.wait_group 0;");
        }
        __syncthreads();

        uint32_t ab = sbase + (c & 1) * 32768;
        uint32_t bb = ab + 16384;

        #pragma unroll
        for (int ks = 0; ks < 4; ks++) {
            uint32_t a[4][4], b[4][2];
            #pragma unroll
            for (int mt = 0; mt < 4; mt++) {
                int row = wm0 + mt * 16 + (lane & 15);
                int col = ks * 16 + ((lane >> 1) & 8);
                uint32_t off = (uint32_t)(row * 128 + col * 2);
                LDSM4(a[mt], ab + SWZ(off));
            }
            #pragma unroll
            for (int np = 0; np < 2; np++) {
                int row = wn0 + np * 16 + (lane & 7) + ((lane & 16) ? 8 : 0);
                int col = ks * 16 + ((lane & 8) ? 8 : 0);
                uint32_t off = (uint32_t)(row * 128 + col * 2);
                uint32_t t[4];
                LDSM4(t, bb + SWZ(off));
                b[2 * np][0] = t[0]; b[2 * np][1] = t[1];
                b[2 * np + 1][0] = t[2]; b[2 * np + 1][1] = t[3];
            }
            #pragma unroll
            for (int mt = 0; mt < 4; mt++)
                #pragma unroll
                for (int nt = 0; nt < 4; nt++)
                    MMA16816(d[mt][nt], a[mt], b[nt]);
        }
        if (c < 7) __syncthreads();
    }

    const int cc0 = n0c + wn0 + (lane & 3) * 2;
    #pragma unroll
    for (int mt = 0; mt < 4; mt++) {
        int grow = m0 + wm0 + mt * 16 + (lane >> 2);
        size_t ob0 = SCATTER ? (size_t)gather_off(grow)     : (size_t)grow * CSTRIDE;
        size_t ob1 = SCATTER ? (size_t)gather_off(grow + 8) : (size_t)(grow + 8) * CSTRIDE;
        #pragma unroll
        for (int nt = 0; nt < 4; nt++) {
            int col = cc0 + nt * 8;
            float bx = bias[col], by = bias[col + 1];
            float2 o0 = {d[mt][nt][0] + bx, d[mt][nt][1] + by};
            float2 o1 = {d[mt][nt][2] + bx, d[mt][nt][3] + by};
            *(float2*)(C + ob0 + col) = o0;
            *(float2*)(C + ob1 + col) = o1;
        }
    }
}

// ---------------------------------------------------------------------------
// K2: tensor-core windowed attention.  q split hi/lo, k hi, v hi;
// P split hi/lo.  2 segments per matmul.
// ---------------------------------------------------------------------------
__global__ __launch_bounds__(128) void attn_kernel(const float* __restrict__ pos_enc)
{
    __shared__ fp16 qh[64 * 40], ql[64 * 40];
    __shared__ fp16 kh[64 * 40];
    __shared__ fp16 vh[32 * 72];               // transposed [dim][col]
    __shared__ float pe[225];
    __shared__ int   rg[64];

    const int w    = blockIdx.x;
    const int h    = blockIdx.y;
    const int tid  = threadIdx.x;
    const int lane = tid & 31;
    const int wp   = tid >> 5;
    const float SCALE = 0.17677669529663687f;

    const float* base = g_qkv + (size_t)w * (64 * 768) + h * 32;

    for (int idx = tid; idx < 2048; idx += 128) {
        int i = idx >> 5, d = idx & 31;
        float qf = base[i * 768 + d] * SCALE;
        fp16 qb = __float2half_rn(qf);
        qh[i * 40 + d] = qb;
        ql[i * 40 + d] = __float2half_rn(qf - __half2float(qb));
        kh[i * 40 + d] = __float2half_rn(base[i * 768 + 256 + d]);
        vh[d * 72 + i] = __float2half_rn(base[i * 768 + 512 + d]);
    }
    for (int idx = tid; idx < 225; idx += 128) pe[idx] = pos_enc[h * 225 + idx];
    if (tid < 64) {
        int wl = w & 63;
        int r  = ((wl >> 3) << 3) + (tid >> 3);
        int c  = ((wl & 7) << 3) + (tid & 7);
        int rr = (r < 56) ? 0 : ((r < 60) ? 1 : 2);
        int cc = (c < 56) ? 0 : ((c < 60) ? 1 : 2);
        rg[tid] = rr * 3 + cc;
    }
    __syncthreads();

    const uint32_t uqh = smem_u32(qh), uql = smem_u32(ql);
    const uint32_t ukh = smem_u32(kh);
    const uint32_t uvh = smem_u32(vh);

    // ---- S = q k^T (2 segments) ----
    float c[8][4];
    #pragma unroll
    for (int j = 0; j < 8; j++)
        #pragma unroll
        for (int q = 0; q < 4; q++) c[j][q] = 0.f;

    uint32_t aqh[2][4], aql[2][4];
    #pragma unroll
    for (int ks = 0; ks < 2; ks++) {
        uint32_t off = (uint32_t)((wp * 16 + (lane & 15)) * 80 +
                                  (ks * 16 + ((lane >> 1) & 8)) * 2);
        LDSM4(aqh[ks], uqh + off);
        LDSM4(aql[ks], uql + off);
    }
    #pragma unroll
    for (int np = 0; np < 4; np++) {
        #pragma unroll
        for (int ks = 0; ks < 2; ks++) {
            uint32_t off = (uint32_t)((np * 16 + (lane & 7) + ((lane & 16) ? 8 : 0)) * 80 +
                                      (ks * 16 + ((lane & 8) ? 8 : 0)) * 2);
            uint32_t bh[4];
            LDSM4(bh, ukh + off);
            #pragma unroll
            for (int n2 = 0; n2 < 2; n2++) {
                MMA16816(c[2 * np + n2], aqh[ks], &bh[2 * n2]);
                MMA16816(c[2 * np + n2], aql[ks], &bh[2 * n2]);
            }
        }
    }

    // ---- bias + mask + softmax on fragments ----
    const int r0 = wp * 16 + (lane >> 2);
    const int r1 = r0 + 8;
    const int yi0 = r0 >> 3, xi0 = r0 & 7, ri0 = rg[r0];
    const int yi1 = r1 >> 3, xi1 = r1 & 7, ri1 = rg[r1];
    float mx0 = -INFINITY, mx1 = -INFINITY;
    #pragma unroll
    for (int j = 0; j < 8; j++) {
        #pragma unroll
        for (int dd = 0; dd < 2; dd++) {
            int col = j * 8 + (lane & 3) * 2 + dd;
            int yj = col >> 3, xj = col & 7;
            int rc = rg[col];
            c[j][dd]     = (rc == ri0)
                ? c[j][dd]     + pe[(yi0 - yj + 7) * 15 + (xi0 - xj + 7)] : -INFINITY;
            c[j][dd + 2] = (rc == ri1)
                ? c[j][dd + 2] + pe[(yi1 - yj + 7) * 15 + (xi1 - xj + 7)] : -INFINITY;
            mx0 = fmaxf(mx0, c[j][dd]);
            mx1 = fmaxf(mx1, c[j][dd + 2]);
        }
    }
    mx0 = fmaxf(mx0, __shfl_xor_sync(0xffffffffu, mx0, 1));
    mx0 = fmaxf(mx0, __shfl_xor_sync(0xffffffffu, mx0, 2));
    mx1 = fmaxf(mx1, __shfl_xor_sync(0xffffffffu, mx1, 1));
    mx1 = fmaxf(mx1, __shfl_xor_sync(0xffffffffu, mx1, 2));
    float s0 = 0.f, s1 = 0.f;
    #pragma unroll
    for (int j = 0; j < 8; j++) {
        #pragma unroll
        for (int dd = 0; dd < 2; dd++) {
            c[j][dd]     = __expf(c[j][dd] - mx0);     s0 += c[j][dd];
            c[j][dd + 2] = __expf(c[j][dd + 2] - mx1); s1 += c[j][dd + 2];
        }
    }
    s0 += __shfl_xor_sync(0xffffffffu, s0, 1);
    s0 += __shfl_xor_sync(0xffffffffu, s0, 2);
    s1 += __shfl_xor_sync(0xffffffffu, s1, 1);
    s1 += __shfl_xor_sync(0xffffffffu, s1, 2);
    const float inv0 = 1.0f / s0, inv1 = 1.0f / s1;
    #pragma unroll
    for (int j = 0; j < 8; j++) {
        c[j][0] *= inv0; c[j][1] *= inv0;
        c[j][2] *= inv1; c[j][3] *= inv1;
    }

    // ---- repack P (C-frag -> A-frag), split hi/lo ----
    uint32_t ph[4][4], pl[4][4];
    #pragma unroll
    for (int t = 0; t < 4; t++) {
        #pragma unroll
        for (int q = 0; q < 4; q++) {
            int nt = 2 * t + (q >> 1);
            int p0 = (q & 1) * 2;
            float x0 = c[nt][p0], x1 = c[nt][p0 + 1];
            float h0 = fhhi(x0), h1 = fhhi(x1);
            ph[t][q] = packh(h0, h1);
            pl[t][q] = packh(x0 - h0, x1 - h1);
        }
    }

    // ---- O = P v (2 segments) ----
    float o[4][4];
    #pragma unroll
    for (int nt = 0; nt < 4; nt++)
        #pragma unroll
        for (int q = 0; q < 4; q++) o[nt][q] = 0.f;

    #pragma unroll
    for (int t = 0; t < 4; t++) {
        #pragma unroll
        for (int nb = 0; nb < 2; nb++) {
            uint32_t off = (uint32_t)((nb * 16 + (lane & 7) + ((lane & 16) ? 8 : 0)) * 144 +
                                      (t * 16 + ((lane & 8) ? 8 : 0)) * 2);
            uint32_t bh[4];
            LDSM4(bh, uvh + off);
            #pragma unroll
            for (int n2 = 0; n2 < 2; n2++) {
                MMA16816(o[2 * nb + n2], ph[t], &bh[2 * n2]);
                MMA16816(o[2 * nb + n2], pl[t], &bh[2 * n2]);
            }
        }
    }

    // ---- epilogue: split fp16 to g_att2 ----
    size_t rb0 = (size_t)(w * 64 + r0) * 512 + h * 32;
    size_t rb1 = (size_t)(w * 64 + r1) * 512 + h * 32;
    #pragma unroll
    for (int nt = 0; nt < 4; nt++) {
        int d0 = nt * 8 + (lane & 3) * 2;
        float a0 = o[nt][0], a1 = o[nt][1], a2 = o[nt][2], a3 = o[nt][3];
        float h0 = fhhi(a0), h1 = fhhi(a1), h2 = fhhi(a2), h3 = fhhi(a3);
        *(uint32_t*)(g_att2 + rb0 + d0)       = packh(h0, h1);
        *(uint32_t*)(g_att2 + rb0 + 256 + d0) = packh(a0 - h0, a1 - h1);
        *(uint32_t*)(g_att2 + rb1 + d0)       = packh(h2, h3);
        *(uint32_t*)(g_att2 + rb1 + 256 + d0) = packh(a2 - h2, a3 - h3);
    }
}

// ---------------------------------------------------------------------------
extern "C" void kernel_launch(void* const* d_in, const int* in_sizes, int n_in,
                              void* d_out, int out_size)
{
    const float* x     = (const float*)d_in[0];
    const float* w_qkv = (const float*)d_in[1];
    const float* b_qkv = (const float*)d_in[2];
    const float* w_out = (const float*)d_in[3];
    const float* b_out = (const float*)d_in[4];
    const float* pos   = (const float*)d_in[5];
    float* out = (float*)d_out;

    const int SMEM = 65536;
    cudaFuncSetAttribute(mma_gemm<6, false>,
                         cudaFuncAttributeMaxDynamicSharedMemorySize, SMEM);
    cudaFuncSetAttribute(mma_gemm<2, true>,
                         cudaFuncAttributeMaxDynamicSharedMemorySize, SMEM);

    convert_kernel<<<32768, 256>>>(x, 131072, 0);
    convert_kernel<<<192,   256>>>(w_qkv, 768, 1);
    convert_kernel<<<64,    256>>>(w_out, 256, 2);
    mma_gemm<6, false><<<dim3(6, 1024), 256, SMEM>>>(b_qkv, nullptr);
    attn_kernel<<<dim3(2048, 8), 128>>>(pos);
    mma_gemm<2, true><<<dim3(2, 1024), 256, SMEM>>>(b_out, out);
}

// round 7
// speedup vs baseline: 2.8053x; 1.0954x over previous
#include <cuda_runtime.h>
#include <cuda_fp16.h>
#include <math.h>
#include <stdint.h>

// ---------------------------------------------------------------------------
// ShiftedWindowAttention (B=32, 64x64, C=256, 8 heads x 32, ws=8, shift=4)
//
// All matmuls on HMMA (mma.sync fp16, fp32 accum) with 2-segment split:
//   A = ah + al (fp16); B ~= bh (fp16)  =>  C = ah*bh + al*bh   (err ~2^-12)
// K0: convert x (gathered) -> [hi|lo] fp16; w_qkv / w_out -> hi fp16
// K1: GEMM x2 @ w2h^T + b_qkv -> fp16 qkv planes directly:
//       g_q [hi|lo] (SCALE folded), g_k hi, g_v hi      (no f32 intermediate)
// K2: windowed attention, tensor-core; fills smem with plain fp16 copies
// K3: GEMM out = att2 @ w3h^T + b_out, rows scattered (inverse roll)
// ---------------------------------------------------------------------------

#define KDIM 256
typedef __half fp16;

__device__ fp16  g_x2  [131072UL * 512];   // x gathered, [hi(256)|lo(256)]
__device__ fp16  g_q   [131072UL * 512];   // q scaled, [hi|lo]
__device__ fp16  g_k   [131072UL * 256];   // k hi
__device__ fp16  g_v   [131072UL * 256];   // v hi
__device__ fp16  g_att2[131072UL * 512];   // attention out, [hi|lo]
__device__ fp16  g_w2  [768 * 256];        // w_qkv hi
__device__ fp16  g_w3  [256 * 256];        // w_out hi

static __device__ __constant__ float SCALEF = 0.17677669529663687f;  // 32^-0.5

__device__ __forceinline__ int gather_off(int gm) {
    int w  = gm >> 6;
    int t  = gm & 63;
    int b  = w >> 6;
    int wl = w & 63;
    int r  = ((wl >> 3) << 3) + (t >> 3);
    int c  = ((wl & 7) << 3) + (t & 7);
    int sr = (r + 4) & 63;
    int sc = (c + 4) & 63;
    return (b * 4096 + sr * 64 + sc) * KDIM;
}

#define SWZ(off) ((off) ^ (((off) >> 3) & 0x70))

__device__ __forceinline__ uint32_t smem_u32(const void* p) {
    uint32_t a;
    asm("{ .reg .u64 t; cvta.to.shared.u64 t, %1; cvt.u32.u64 %0, t; }"
        : "=r"(a) : "l"(p));
    return a;
}

#define LDSM4(r, addr)                                                         \
    asm volatile("ldmatrix.sync.aligned.m8n8.x4.shared.b16 {%0,%1,%2,%3}, [%4];"\
                 : "=r"((r)[0]), "=r"((r)[1]), "=r"((r)[2]), "=r"((r)[3])      \
                 : "r"(addr))

#define MMA16816(d, a, b)                                                      \
    asm volatile("mma.sync.aligned.m16n8k16.row.col.f32.f16.f16.f32 "          \
                 "{%0,%1,%2,%3}, {%4,%5,%6,%7}, {%8,%9}, {%0,%1,%2,%3};"       \
                 : "+f"((d)[0]), "+f"((d)[1]), "+f"((d)[2]), "+f"((d)[3])      \
                 : "r"((a)[0]), "r"((a)[1]), "r"((a)[2]), "r"((a)[3]),         \
                   "r"((b)[0]), "r"((b)[1]))

__device__ __forceinline__ uint32_t packh(float lo, float hi) {
    __half2 h = __floats2half2_rn(lo, hi);
    return *(uint32_t*)&h;
}
__device__ __forceinline__ float fhhi(float x) {
    return __half2float(__float2half_rn(x));
}

// ---------------------------------------------------------------------------
// K0: conversion. mode 0: x (gathered) -> g_x2 [hi|lo]
//                 mode 1: w_qkv -> g_w2 hi,  mode 2: w_out -> g_w3 hi
// ---------------------------------------------------------------------------
__global__ void convert_kernel(const float* __restrict__ src, int nrows, int mode)
{
    int idx = blockIdx.x * blockDim.x + threadIdx.x;
    if (idx >= nrows * 64) return;
    int row = idx >> 6;
    int c   = (idx & 63) << 2;
    const float* sp = src + (mode == 0 ? gather_off(row) : row * 256) + c;
    float4 v = *(const float4*)sp;

    float vs[4] = {v.x, v.y, v.z, v.w};
    fp16 __align__(8) hi[4];
    #pragma unroll
    for (int i = 0; i < 4; i++) hi[i] = __float2half_rn(vs[i]);

    if (mode == 0) {
        fp16 __align__(8) lo[4];
        #pragma unroll
        for (int i = 0; i < 4; i++)
            lo[i] = __float2half_rn(vs[i] - __half2float(hi[i]));
        *(uint2*)(g_x2 + (size_t)row * 512 + c)       = *(uint2*)hi;
        *(uint2*)(g_x2 + (size_t)row * 512 + 256 + c) = *(uint2*)lo;
    } else {
        fp16* dst = (mode == 1) ? g_w2 : g_w3;
        *(uint2*)(dst + (size_t)row * 256 + c) = *(uint2*)hi;
    }
}

// ---------------------------------------------------------------------------
// mma.sync GEMM.  C[128 x 128] per CTA, 8 warps, warp tile 64x32.
// K'' = 512 = 2 segments x 256 (A: hi then lo; B: hi both);
// chunk = 64 cols, 2-stage cp.async pipeline.
// QKV mode (!SCATTER): epilogue writes fp16 planes g_q/g_k/g_v.
// SCATTER mode: f32 output with inverse-roll row scatter.
// ---------------------------------------------------------------------------
template <int NT, bool SCATTER>
__global__ __launch_bounds__(256, 2) void mma_gemm(const float* __restrict__ bias,
                                                   float* __restrict__ Cout)
{
    extern __shared__ __align__(1024) char smem[];
    const fp16* Ag = SCATTER ? g_att2 : g_x2;
    const fp16* Bg = SCATTER ? g_w3   : g_w2;

    const int tid  = threadIdx.x;
    const int lane = tid & 31;
    const int warp = tid >> 5;
    const int m0   = blockIdx.y * 128;
    const int n0c  = blockIdx.x * 128;
    const uint32_t sbase = smem_u32(smem);

    auto stage = [&](int c, int buf) {
        int kin  = (c & 3) * 64;
        int acol = (c >> 2) * 256 + kin;
        uint32_t ab = sbase + buf * 32768;
        uint32_t bb = ab + 16384;
        #pragma unroll
        for (int i = 0; i < 4; i++) {
            int idx = tid + i * 256;
            int r  = idx >> 3;
            int ch = idx & 7;
            uint32_t off = (uint32_t)(r * 128 + ch * 16);
            const fp16* as = Ag + (size_t)(m0 + r) * 512 + acol + ch * 8;
            const fp16* bs = Bg + (size_t)(n0c + r) * 256 + kin + ch * 8;
            asm volatile("cp.async.cg.shared.global [%0], [%1], 16;"
                         :: "r"(ab + SWZ(off)), "l"(as));
            asm volatile("cp.async.cg.shared.global [%0], [%1], 16;"
                         :: "r"(bb + SWZ(off)), "l"(bs));
        }
        asm volatile("cp.async.commit_group;");
    };

    float d[4][4][4];
    #pragma unroll
    for (int mt = 0; mt < 4; mt++)
        #pragma unroll
        for (int nt = 0; nt < 4; nt++)
            #pragma unroll
            for (int j = 0; j < 4; j++) d[mt][nt][j] = 0.f;

    const int wm0 = (warp >> 2) * 64;
    const int wn0 = (warp & 3) * 32;

    stage(0, 0);
    for (int c = 0; c < 8; c++) {
        if (c < 7) {
            stage(c + 1, (c + 1) & 1);
            asm volatile("cp.async.wait_group 1;");
        } else {
            asm volatile("cp.async.wait_group 0;");
        }
        __syncthreads();

        uint32_t ab = sbase + (c & 1) * 32768;
        uint32_t bb = ab + 16384;

        #pragma unroll
        for (int ks = 0; ks < 4; ks++) {
            uint32_t a[4][4], b[4][2];
            #pragma unroll
            for (int mt = 0; mt < 4; mt++) {
                int row = wm0 + mt * 16 + (lane & 15);
                int col = ks * 16 + ((lane >> 1) & 8);
                uint32_t off = (uint32_t)(row * 128 + col * 2);
                LDSM4(a[mt], ab + SWZ(off));
            }
            #pragma unroll
            for (int np = 0; np < 2; np++) {
                int row = wn0 + np * 16 + (lane & 7) + ((lane & 16) ? 8 : 0);
                int col = ks * 16 + ((lane & 8) ? 8 : 0);
                uint32_t off = (uint32_t)(row * 128 + col * 2);
                uint32_t t[4];
                LDSM4(t, bb + SWZ(off));
                b[2 * np][0] = t[0]; b[2 * np][1] = t[1];
                b[2 * np + 1][0] = t[2]; b[2 * np + 1][1] = t[3];
            }
            #pragma unroll
            for (int mt = 0; mt < 4; mt++)
                #pragma unroll
                for (int nt = 0; nt < 4; nt++)
                    MMA16816(d[mt][nt], a[mt], b[nt]);
        }
        if (c < 7) __syncthreads();
    }

    const int cc0 = n0c + wn0 + (lane & 3) * 2;
    #pragma unroll
    for (int mt = 0; mt < 4; mt++) {
        int g0 = m0 + wm0 + mt * 16 + (lane >> 2);
        if (SCATTER) {
            size_t ob0 = (size_t)gather_off(g0);
            size_t ob1 = (size_t)gather_off(g0 + 8);
            #pragma unroll
            for (int nt = 0; nt < 4; nt++) {
                int col = cc0 + nt * 8;
                float bx = bias[col], by = bias[col + 1];
                float2 o0 = {d[mt][nt][0] + bx, d[mt][nt][1] + by};
                float2 o1 = {d[mt][nt][2] + bx, d[mt][nt][3] + by};
                *(float2*)(Cout + ob0 + col) = o0;
                *(float2*)(Cout + ob1 + col) = o1;
            }
        } else {
            #pragma unroll
            for (int nt = 0; nt < 4; nt++) {
                int col = cc0 + nt * 8;
                float bx = bias[col], by = bias[col + 1];
                float v0 = d[mt][nt][0] + bx, v1 = d[mt][nt][1] + by;
                float v2 = d[mt][nt][2] + bx, v3 = d[mt][nt][3] + by;
                if (n0c < 256) {            // q: scale + split hi/lo
                    v0 *= SCALEF; v1 *= SCALEF; v2 *= SCALEF; v3 *= SCALEF;
                    float h0 = fhhi(v0), h1 = fhhi(v1), h2 = fhhi(v2), h3 = fhhi(v3);
                    *(uint32_t*)(g_q + (size_t)g0 * 512 + col)             = packh(h0, h1);
                    *(uint32_t*)(g_q + (size_t)g0 * 512 + 256 + col)       = packh(v0 - h0, v1 - h1);
                    *(uint32_t*)(g_q + (size_t)(g0 + 8) * 512 + col)       = packh(h2, h3);
                    *(uint32_t*)(g_q + (size_t)(g0 + 8) * 512 + 256 + col) = packh(v2 - h2, v3 - h3);
                } else if (n0c < 512) {     // k: hi only
                    int ck = col - 256;
                    *(uint32_t*)(g_k + (size_t)g0 * 256 + ck)       = packh(v0, v1);
                    *(uint32_t*)(g_k + (size_t)(g0 + 8) * 256 + ck) = packh(v2, v3);
                } else {                    // v: hi only
                    int cv = col - 512;
                    *(uint32_t*)(g_v + (size_t)g0 * 256 + cv)       = packh(v0, v1);
                    *(uint32_t*)(g_v + (size_t)(g0 + 8) * 256 + cv) = packh(v2, v3);
                }
            }
        }
    }
}

// ---------------------------------------------------------------------------
// K2: tensor-core windowed attention.  fp16 inputs, plain copies into smem.
// ---------------------------------------------------------------------------
__global__ __launch_bounds__(128) void attn_kernel(const float* __restrict__ pos_enc)
{
    __shared__ fp16 qh[64 * 40], ql[64 * 40];
    __shared__ fp16 kh[64 * 40];
    __shared__ fp16 vh[32 * 72];               // transposed [dim][col]
    __shared__ float pe[225];
    __shared__ int   rg[64];

    const int w    = blockIdx.x;
    const int h    = blockIdx.y;
    const int tid  = threadIdx.x;
    const int lane = tid & 31;
    const int wp   = tid >> 5;

    const size_t rowbase = (size_t)(w * 64);

    // q hi/lo: 512 x 16B chunks
    for (int t = tid; t < 512; t += 128) {
        int plane = t >> 8;
        int u = t & 255;
        int i = u >> 2;
        int d0 = (u & 3) * 8;
        uint4 v = *(const uint4*)(g_q + (rowbase + i) * 512 + plane * 256 + h * 32 + d0);
        *(uint4*)((plane ? ql : qh) + i * 40 + d0) = v;
    }
    // k hi: 256 chunks
    for (int t = tid; t < 256; t += 128) {
        int i = t >> 2, d0 = (t & 3) * 8;
        uint4 v = *(const uint4*)(g_k + (rowbase + i) * 256 + h * 32 + d0);
        *(uint4*)(kh + i * 40 + d0) = v;
    }
    // v hi: 256 chunks, transposed into [dim][token]
    for (int t = tid; t < 256; t += 128) {
        int i = t >> 2, d0 = (t & 3) * 8;
        fp16 tmp[8];
        *(uint4*)tmp = *(const uint4*)(g_v + (rowbase + i) * 256 + h * 32 + d0);
        #pragma unroll
        for (int e = 0; e < 8; e++) vh[(d0 + e) * 72 + i] = tmp[e];
    }
    for (int idx = tid; idx < 225; idx += 128) pe[idx] = pos_enc[h * 225 + idx];
    if (tid < 64) {
        int wl = w & 63;
        int r  = ((wl >> 3) << 3) + (tid >> 3);
        int c  = ((wl & 7) << 3) + (tid & 7);
        int rr = (r < 56) ? 0 : ((r < 60) ? 1 : 2);
        int cc = (c < 56) ? 0 : ((c < 60) ? 1 : 2);
        rg[tid] = rr * 3 + cc;
    }
    __syncthreads();

    const uint32_t uqh = smem_u32(qh), uql = smem_u32(ql);
    const uint32_t ukh = smem_u32(kh);
    const uint32_t uvh = smem_u32(vh);

    // ---- S = q k^T (2 segments) ----
    float c[8][4];
    #pragma unroll
    for (int j = 0; j < 8; j++)
        #pragma unroll
        for (int q = 0; q < 4; q++) c[j][q] = 0.f;

    uint32_t aqh[2][4], aql[2][4];
    #pragma unroll
    for (int ks = 0; ks < 2; ks++) {
        uint32_t off = (uint32_t)((wp * 16 + (lane & 15)) * 80 +
                                  (ks * 16 + ((lane >> 1) & 8)) * 2);
        LDSM4(aqh[ks], uqh + off);
        LDSM4(aql[ks], uql + off);
    }
    #pragma unroll
    for (int np = 0; np < 4; np++) {
        #pragma unroll
        for (int ks = 0; ks < 2; ks++) {
            uint32_t off = (uint32_t)((np * 16 + (lane & 7) + ((lane & 16) ? 8 : 0)) * 80 +
                                      (ks * 16 + ((lane & 8) ? 8 : 0)) * 2);
            uint32_t bh[4];
            LDSM4(bh, ukh + off);
            #pragma unroll
            for (int n2 = 0; n2 < 2; n2++) {
                MMA16816(c[2 * np + n2], aqh[ks], &bh[2 * n2]);
                MMA16816(c[2 * np + n2], aql[ks], &bh[2 * n2]);
            }
        }
    }

    // ---- bias + mask + softmax on fragments ----
    const int r0 = wp * 16 + (lane >> 2);
    const int r1 = r0 + 8;
    const int yi0 = r0 >> 3, xi0 = r0 & 7, ri0 = rg[r0];
    const int yi1 = r1 >> 3, xi1 = r1 & 7, ri1 = rg[r1];
    float mx0 = -INFINITY, mx1 = -INFINITY;
    #pragma unroll
    for (int j = 0; j < 8; j++) {
        #pragma unroll
        for (int dd = 0; dd < 2; dd++) {
            int col = j * 8 + (lane & 3) * 2 + dd;
            int yj = col >> 3, xj = col & 7;
            int rc = rg[col];
            c[j][dd]     = (rc == ri0)
                ? c[j][dd]     + pe[(yi0 - yj + 7) * 15 + (xi0 - xj + 7)] : -INFINITY;
            c[j][dd + 2] = (rc == ri1)
                ? c[j][dd + 2] + pe[(yi1 - yj + 7) * 15 + (xi1 - xj + 7)] : -INFINITY;
            mx0 = fmaxf(mx0, c[j][dd]);
            mx1 = fmaxf(mx1, c[j][dd + 2]);
        }
    }
    mx0 = fmaxf(mx0, __shfl_xor_sync(0xffffffffu, mx0, 1));
    mx0 = fmaxf(mx0, __shfl_xor_sync(0xffffffffu, mx0, 2));
    mx1 = fmaxf(mx1, __shfl_xor_sync(0xffffffffu, mx1, 1));
    mx1 = fmaxf(mx1, __shfl_xor_sync(0xffffffffu, mx1, 2));
    float s0 = 0.f, s1 = 0.f;
    #pragma unroll
    for (int j = 0; j < 8; j++) {
        #pragma unroll
        for (int dd = 0; dd < 2; dd++) {
            c[j][dd]     = __expf(c[j][dd] - mx0);     s0 += c[j][dd];
            c[j][dd + 2] = __expf(c[j][dd + 2] - mx1); s1 += c[j][dd + 2];
        }
    }
    s0 += __shfl_xor_sync(0xffffffffu, s0, 1);
    s0 += __shfl_xor_sync(0xffffffffu, s0, 2);
    s1 += __shfl_xor_sync(0xffffffffu, s1, 1);
    s1 += __shfl_xor_sync(0xffffffffu, s1, 2);
    const float inv0 = 1.0f / s0, inv1 = 1.0f / s1;
    #pragma unroll
    for (int j = 0; j < 8; j++) {
        c[j][0] *= inv0; c[j][1] *= inv0;
        c[j][2] *= inv1; c[j][3] *= inv1;
    }

    // ---- repack P (C-frag -> A-frag), split hi/lo ----
    uint32_t ph[4][4], pl[4][4];
    #pragma unroll
    for (int t = 0; t < 4; t++) {
        #pragma unroll
        for (int q = 0; q < 4; q++) {
            int nt = 2 * t + (q >> 1);
            int p0 = (q & 1) * 2;
            float x0 = c[nt][p0], x1 = c[nt][p0 + 1];
            float h0 = fhhi(x0), h1 = fhhi(x1);
            ph[t][q] = packh(h0, h1);
            pl[t][q] = packh(x0 - h0, x1 - h1);
        }
    }

    // ---- O = P v (2 segments) ----
    float o[4][4];
    #pragma unroll
    for (int nt = 0; nt < 4; nt++)
        #pragma unroll
        for (int q = 0; q < 4; q++) o[nt][q] = 0.f;

    #pragma unroll
    for (int t = 0; t < 4; t++) {
        #pragma unroll
        for (int nb = 0; nb < 2; nb++) {
            uint32_t off = (uint32_t)((nb * 16 + (lane & 7) + ((lane & 16) ? 8 : 0)) * 144 +
                                      (t * 16 + ((lane & 8) ? 8 : 0)) * 2);
            uint32_t bh[4];
            LDSM4(bh, uvh + off);
            #pragma unroll
            for (int n2 = 0; n2 < 2; n2++) {
                MMA16816(o[2 * nb + n2], ph[t], &bh[2 * n2]);
                MMA16816(o[2 * nb + n2], pl[t], &bh[2 * n2]);
            }
        }
    }

    // ---- epilogue: split fp16 to g_att2 ----
    size_t rb0 = (size_t)(w * 64 + r0) * 512 + h * 32;
    size_t rb1 = (size_t)(w * 64 + r1) * 512 + h * 32;
    #pragma unroll
    for (int nt = 0; nt < 4; nt++) {
        int d0 = nt * 8 + (lane & 3) * 2;
        float a0 = o[nt][0], a1 = o[nt][1], a2 = o[nt][2], a3 = o[nt][3];
        float h0 = fhhi(a0), h1 = fhhi(a1), h2 = fhhi(a2), h3 = fhhi(a3);
        *(uint32_t*)(g_att2 + rb0 + d0)       = packh(h0, h1);
        *(uint32_t*)(g_att2 + rb0 + 256 + d0) = packh(a0 - h0, a1 - h1);
        *(uint32_t*)(g_att2 + rb1 + d0)       = packh(h2, h3);
        *(uint32_t*)(g_att2 + rb1 + 256 + d0) = packh(a2 - h2, a3 - h3);
    }
}

// ---------------------------------------------------------------------------
extern "C" void kernel_launch(void* const* d_in, const int* in_sizes, int n_in,
                              void* d_out, int out_size)
{
    const float* x     = (const float*)d_in[0];
    const float* w_qkv = (const float*)d_in[1];
    const float* b_qkv = (const float*)d_in[2];
    const float* w_out = (const float*)d_in[3];
    const float* b_out = (const float*)d_in[4];
    const float* pos   = (const float*)d_in[5];
    float* out = (float*)d_out;

    const int SMEM = 65536;
    cudaFuncSetAttribute(mma_gemm<6, false>,
                         cudaFuncAttributeMaxDynamicSharedMemorySize, SMEM);
    cudaFuncSetAttribute(mma_gemm<2, true>,
                         cudaFuncAttributeMaxDynamicSharedMemorySize, SMEM);

    convert_kernel<<<32768, 256>>>(x, 131072, 0);
    convert_kernel<<<192,   256>>>(w_qkv, 768, 1);
    convert_kernel<<<64,    256>>>(w_out, 256, 2);
    mma_gemm<6, false><<<dim3(6, 1024), 256, SMEM>>>(b_qkv, nullptr);
    attn_kernel<<<dim3(2048, 8), 128>>>(pos);
    mma_gemm<2, true><<<dim3(2, 1024), 256, SMEM>>>(b_out, out);
}

// round 8
// speedup vs baseline: 3.5932x; 1.2809x over previous
#include <cuda_runtime.h>
#include <cuda_fp16.h>
#include <math.h>
#include <stdint.h>

// ---------------------------------------------------------------------------
// ShiftedWindowAttention (B=32, 64x64, C=256, 8 heads x 32, ws=8, shift=4)
//
// All matmuls on HMMA (mma.sync fp16, fp32 accum). Split-fp16 only where the
// extra precision survives downstream:
//   K1 q tiles: A = hi+lo (2 seg); k/v tiles: A = hi (1 seg, output is fp16)
//   K2 scores:  q hi/lo x k hi; P split hi/lo x v hi; O stored fp16-hi only
//   K3:         att2(hi) x w_out(hi), 1 segment (output tolerance 1e-3)
// ---------------------------------------------------------------------------

#define KDIM 256
typedef __half fp16;

__device__ fp16  g_x2  [131072UL * 512];   // x gathered, [hi(256)|lo(256)]
__device__ fp16  g_q   [131072UL * 512];   // q scaled, [hi|lo]
__device__ fp16  g_k   [131072UL * 256];   // k hi
__device__ fp16  g_v   [131072UL * 256];   // v hi
__device__ fp16  g_att2[131072UL * 256];   // attention out, hi only
__device__ fp16  g_w2  [768 * 256];        // w_qkv hi
__device__ fp16  g_w3  [256 * 256];        // w_out hi

static __device__ __constant__ float SCALEF = 0.17677669529663687f;  // 32^-0.5

__device__ __forceinline__ int gather_off(int gm) {
    int w  = gm >> 6;
    int t  = gm & 63;
    int b  = w >> 6;
    int wl = w & 63;
    int r  = ((wl >> 3) << 3) + (t >> 3);
    int c  = ((wl & 7) << 3) + (t & 7);
    int sr = (r + 4) & 63;
    int sc = (c + 4) & 63;
    return (b * 4096 + sr * 64 + sc) * KDIM;
}

#define SWZ(off) ((off) ^ (((off) >> 3) & 0x70))

__device__ __forceinline__ uint32_t smem_u32(const void* p) {
    uint32_t a;
    asm("{ .reg .u64 t; cvta.to.shared.u64 t, %1; cvt.u32.u64 %0, t; }"
        : "=r"(a) : "l"(p));
    return a;
}

#define LDSM4(r, addr)                                                         \
    asm volatile("ldmatrix.sync.aligned.m8n8.x4.shared.b16 {%0,%1,%2,%3}, [%4];"\
                 : "=r"((r)[0]), "=r"((r)[1]), "=r"((r)[2]), "=r"((r)[3])      \
                 : "r"(addr))

#define MMA16816(d, a, b)                                                      \
    asm volatile("mma.sync.aligned.m16n8k16.row.col.f32.f16.f16.f32 "          \
                 "{%0,%1,%2,%3}, {%4,%5,%6,%7}, {%8,%9}, {%0,%1,%2,%3};"       \
                 : "+f"((d)[0]), "+f"((d)[1]), "+f"((d)[2]), "+f"((d)[3])      \
                 : "r"((a)[0]), "r"((a)[1]), "r"((a)[2]), "r"((a)[3]),         \
                   "r"((b)[0]), "r"((b)[1]))

__device__ __forceinline__ uint32_t packh(float lo, float hi) {
    __half2 h = __floats2half2_rn(lo, hi);
    return *(uint32_t*)&h;
}
__device__ __forceinline__ float fhhi(float x) {
    return __half2float(__float2half_rn(x));
}

// ---------------------------------------------------------------------------
// K0: conversion. mode 0: x (gathered) -> g_x2 [hi|lo]
//                 mode 1: w_qkv -> g_w2 hi,  mode 2: w_out -> g_w3 hi
// ---------------------------------------------------------------------------
__global__ void convert_kernel(const float* __restrict__ src, int nrows, int mode)
{
    int idx = blockIdx.x * blockDim.x + threadIdx.x;
    if (idx >= nrows * 64) return;
    int row = idx >> 6;
    int c   = (idx & 63) << 2;
    const float* sp = src + (mode == 0 ? gather_off(row) : row * 256) + c;
    float4 v = *(const float4*)sp;

    float vs[4] = {v.x, v.y, v.z, v.w};
    fp16 __align__(8) hi[4];
    #pragma unroll
    for (int i = 0; i < 4; i++) hi[i] = __float2half_rn(vs[i]);

    if (mode == 0) {
        fp16 __align__(8) lo[4];
        #pragma unroll
        for (int i = 0; i < 4; i++)
            lo[i] = __float2half_rn(vs[i] - __half2float(hi[i]));
        *(uint2*)(g_x2 + (size_t)row * 512 + c)       = *(uint2*)hi;
        *(uint2*)(g_x2 + (size_t)row * 512 + 256 + c) = *(uint2*)lo;
    } else {
        fp16* dst = (mode == 1) ? g_w2 : g_w3;
        *(uint2*)(dst + (size_t)row * 256 + c) = *(uint2*)hi;
    }
}

// ---------------------------------------------------------------------------
// mma.sync GEMM.  C[128 x 128] per CTA, 8 warps, warp tile 64x32.
// Chunks of 64 K-cols, 2-stage cp.async pipeline.
// Segment count per N-tile: K1 q tiles (n0c<256) 8 chunks (A hi+lo),
// K1 k/v tiles and all of K3: 4 chunks (A hi only).
// ---------------------------------------------------------------------------
template <int NT, int ASTR, bool SCATTER>
__global__ __launch_bounds__(256, 2) void mma_gemm(const float* __restrict__ bias,
                                                   float* __restrict__ Cout)
{
    extern __shared__ __align__(1024) char smem[];
    const fp16* Ag = SCATTER ? g_att2 : g_x2;
    const fp16* Bg = SCATTER ? g_w3   : g_w2;

    const int tid  = threadIdx.x;
    const int lane = tid & 31;
    const int warp = tid >> 5;
    const int m0   = blockIdx.y * 128;
    const int n0c  = blockIdx.x * 128;
    const uint32_t sbase = smem_u32(smem);

    const int NC = (!SCATTER && n0c < 256) ? 8 : 4;

    auto stage = [&](int c, int buf) {
        int kin  = (c & 3) * 64;
        int acol = (c >> 2) * 256 + kin;
        uint32_t ab = sbase + buf * 32768;
        uint32_t bb = ab + 16384;
        #pragma unroll
        for (int i = 0; i < 4; i++) {
            int idx = tid + i * 256;
            int r  = idx >> 3;
            int ch = idx & 7;
            uint32_t off = (uint32_t)(r * 128 + ch * 16);
            const fp16* as = Ag + (size_t)(m0 + r) * ASTR + acol + ch * 8;
            const fp16* bs = Bg + (size_t)(n0c + r) * 256 + kin + ch * 8;
            asm volatile("cp.async.cg.shared.global [%0], [%1], 16;"
                         :: "r"(ab + SWZ(off)), "l"(as));
            asm volatile("cp.async.cg.shared.global [%0], [%1], 16;"
                         :: "r"(bb + SWZ(off)), "l"(bs));
        }
        asm volatile("cp.async.commit_group;");
    };

    float d[4][4][4];
    #pragma unroll
    for (int mt = 0; mt < 4; mt++)
        #pragma unroll
        for (int nt = 0; nt < 4; nt++)
            #pragma unroll
            for (int j = 0; j < 4; j++) d[mt][nt][j] = 0.f;

    const int wm0 = (warp >> 2) * 64;
    const int wn0 = (warp & 3) * 32;

    stage(0, 0);
    #pragma unroll 1
    for (int c = 0; c < NC; c++) {
        if (c < NC - 1) {
            stage(c + 1, (c + 1) & 1);
            asm volatile("cp.async.wait_group 1;");
        } else {
            asm volatile("cp.async.wait_group 0;");
        }
        __syncthreads();

        uint32_t ab = sbase + (c & 1) * 32768;
        uint32_t bb = ab + 16384;

        #pragma unroll
        for (int ks = 0; ks < 4; ks++) {
            uint32_t a[4][4], b[4][2];
            #pragma unroll
            for (int mt = 0; mt < 4; mt++) {
                int row = wm0 + mt * 16 + (lane & 15);
                int col = ks * 16 + ((lane >> 1) & 8);
                uint32_t off = (uint32_t)(row * 128 + col * 2);
                LDSM4(a[mt], ab + SWZ(off));
            }
            #pragma unroll
            for (int np = 0; np < 2; np++) {
                int row = wn0 + np * 16 + (lane & 7) + ((lane & 16) ? 8 : 0);
                int col = ks * 16 + ((lane & 8) ? 8 : 0);
                uint32_t off = (uint32_t)(row * 128 + col * 2);
                uint32_t t[4];
                LDSM4(t, bb + SWZ(off));
                b[2 * np][0] = t[0]; b[2 * np][1] = t[1];
                b[2 * np + 1][0] = t[2]; b[2 * np + 1][1] = t[3];
            }
            #pragma unroll
            for (int mt = 0; mt < 4; mt++)
                #pragma unroll
                for (int nt = 0; nt < 4; nt++)
                    MMA16816(d[mt][nt], a[mt], b[nt]);
        }
        if (c < NC - 1) __syncthreads();
    }

    const int cc0 = n0c + wn0 + (lane & 3) * 2;
    #pragma unroll
    for (int mt = 0; mt < 4; mt++) {
        int g0 = m0 + wm0 + mt * 16 + (lane >> 2);
        if (SCATTER) {
            size_t ob0 = (size_t)gather_off(g0);
            size_t ob1 = (size_t)gather_off(g0 + 8);
            #pragma unroll
            for (int nt = 0; nt < 4; nt++) {
                int col = cc0 + nt * 8;
                float bx = bias[col], by = bias[col + 1];
                float2 o0 = {d[mt][nt][0] + bx, d[mt][nt][1] + by};
                float2 o1 = {d[mt][nt][2] + bx, d[mt][nt][3] + by};
                *(float2*)(Cout + ob0 + col) = o0;
                *(float2*)(Cout + ob1 + col) = o1;
            }
        } else {
            #pragma unroll
            for (int nt = 0; nt < 4; nt++) {
                int col = cc0 + nt * 8;
                float bx = bias[col], by = bias[col + 1];
                float v0 = d[mt][nt][0] + bx, v1 = d[mt][nt][1] + by;
                float v2 = d[mt][nt][2] + bx, v3 = d[mt][nt][3] + by;
                if (n0c < 256) {            // q: scale + split hi/lo
                    v0 *= SCALEF; v1 *= SCALEF; v2 *= SCALEF; v3 *= SCALEF;
                    float h0 = fhhi(v0), h1 = fhhi(v1), h2 = fhhi(v2), h3 = fhhi(v3);
                    *(uint32_t*)(g_q + (size_t)g0 * 512 + col)             = packh(h0, h1);
                    *(uint32_t*)(g_q + (size_t)g0 * 512 + 256 + col)       = packh(v0 - h0, v1 - h1);
                    *(uint32_t*)(g_q + (size_t)(g0 + 8) * 512 + col)       = packh(h2, h3);
                    *(uint32_t*)(g_q + (size_t)(g0 + 8) * 512 + 256 + col) = packh(v2 - h2, v3 - h3);
                } else if (n0c < 512) {     // k: hi only
                    int ck = col - 256;
                    *(uint32_t*)(g_k + (size_t)g0 * 256 + ck)       = packh(v0, v1);
                    *(uint32_t*)(g_k + (size_t)(g0 + 8) * 256 + ck) = packh(v2, v3);
                } else {                    // v: hi only
                    int cv = col - 512;
                    *(uint32_t*)(g_v + (size_t)g0 * 256 + cv)       = packh(v0, v1);
                    *(uint32_t*)(g_v + (size_t)(g0 + 8) * 256 + cv) = packh(v2, v3);
                }
            }
        }
    }
}

// ---------------------------------------------------------------------------
// K2: tensor-core windowed attention.  fp16 inputs, plain copies into smem.
// Output: fp16 hi only into g_att2 (stride 256).
// ---------------------------------------------------------------------------
__global__ __launch_bounds__(128) void attn_kernel(const float* __restrict__ pos_enc)
{
    __shared__ fp16 qh[64 * 40], ql[64 * 40];
    __shared__ fp16 kh[64 * 40];
    __shared__ fp16 vh[32 * 72];               // transposed [dim][col]
    __shared__ float pe[225];
    __shared__ int   rg[64];

    const int w    = blockIdx.x;
    const int h    = blockIdx.y;
    const int tid  = threadIdx.x;
    const int lane = tid & 31;
    const int wp   = tid >> 5;

    const size_t rowbase = (size_t)(w * 64);

    for (int t = tid; t < 512; t += 128) {
        int plane = t >> 8;
        int u = t & 255;
        int i = u >> 2;
        int d0 = (u & 3) * 8;
        uint4 v = *(const uint4*)(g_q + (rowbase + i) * 512 + plane * 256 + h * 32 + d0);
        *(uint4*)((plane ? ql : qh) + i * 40 + d0) = v;
    }
    for (int t = tid; t < 256; t += 128) {
        int i = t >> 2, d0 = (t & 3) * 8;
        uint4 v = *(const uint4*)(g_k + (rowbase + i) * 256 + h * 32 + d0);
        *(uint4*)(kh + i * 40 + d0) = v;
    }
    for (int t = tid; t < 256; t += 128) {
        int i = t >> 2, d0 = (t & 3) * 8;
        fp16 tmp[8];
        *(uint4*)tmp = *(const uint4*)(g_v + (rowbase + i) * 256 + h * 32 + d0);
        #pragma unroll
        for (int e = 0; e < 8; e++) vh[(d0 + e) * 72 + i] = tmp[e];
    }
    for (int idx = tid; idx < 225; idx += 128) pe[idx] = pos_enc[h * 225 + idx];
    if (tid < 64) {
        int wl = w & 63;
        int r  = ((wl >> 3) << 3) + (tid >> 3);
        int c  = ((wl & 7) << 3) + (tid & 7);
        int rr = (r < 56) ? 0 : ((r < 60) ? 1 : 2);
        int cc = (c < 56) ? 0 : ((c < 60) ? 1 : 2);
        rg[tid] = rr * 3 + cc;
    }
    __syncthreads();

    const uint32_t uqh = smem_u32(qh), uql = smem_u32(ql);
    const uint32_t ukh = smem_u32(kh);
    const uint32_t uvh = smem_u32(vh);

    // ---- S = q k^T (2 segments) ----
    float c[8][4];
    #pragma unroll
    for (int j = 0; j < 8; j++)
        #pragma unroll
        for (int q = 0; q < 4; q++) c[j][q] = 0.f;

    uint32_t aqh[2][4], aql[2][4];
    #pragma unroll
    for (int ks = 0; ks < 2; ks++) {
        uint32_t off = (uint32_t)((wp * 16 + (lane & 15)) * 80 +
                                  (ks * 16 + ((lane >> 1) & 8)) * 2);
        LDSM4(aqh[ks], uqh + off);
        LDSM4(aql[ks], uql + off);
    }
    #pragma unroll
    for (int np = 0; np < 4; np++) {
        #pragma unroll
        for (int ks = 0; ks < 2; ks++) {
            uint32_t off = (uint32_t)((np * 16 + (lane & 7) + ((lane & 16) ? 8 : 0)) * 80 +
                                      (ks * 16 + ((lane & 8) ? 8 : 0)) * 2);
            uint32_t bh[4];
            LDSM4(bh, ukh + off);
            #pragma unroll
            for (int n2 = 0; n2 < 2; n2++) {
                MMA16816(c[2 * np + n2], aqh[ks], &bh[2 * n2]);
                MMA16816(c[2 * np + n2], aql[ks], &bh[2 * n2]);
            }
        }
    }

    // ---- bias + mask + softmax on fragments ----
    const int r0 = wp * 16 + (lane >> 2);
    const int r1 = r0 + 8;
    const int yi0 = r0 >> 3, xi0 = r0 & 7, ri0 = rg[r0];
    const int yi1 = r1 >> 3, xi1 = r1 & 7, ri1 = rg[r1];
    float mx0 = -INFINITY, mx1 = -INFINITY;
    #pragma unroll
    for (int j = 0; j < 8; j++) {
        #pragma unroll
        for (int dd = 0; dd < 2; dd++) {
            int col = j * 8 + (lane & 3) * 2 + dd;
            int yj = col >> 3, xj = col & 7;
            int rc = rg[col];
            c[j][dd]     = (rc == ri0)
                ? c[j][dd]     + pe[(yi0 - yj + 7) * 15 + (xi0 - xj + 7)] : -INFINITY;
            c[j][dd + 2] = (rc == ri1)
                ? c[j][dd + 2] + pe[(yi1 - yj + 7) * 15 + (xi1 - xj + 7)] : -INFINITY;
            mx0 = fmaxf(mx0, c[j][dd]);
            mx1 = fmaxf(mx1, c[j][dd + 2]);
        }
    }
    mx0 = fmaxf(mx0, __shfl_xor_sync(0xffffffffu, mx0, 1));
    mx0 = fmaxf(mx0, __shfl_xor_sync(0xffffffffu, mx0, 2));
    mx1 = fmaxf(mx1, __shfl_xor_sync(0xffffffffu, mx1, 1));
    mx1 = fmaxf(mx1, __shfl_xor_sync(0xffffffffu, mx1, 2));
    float s0 = 0.f, s1 = 0.f;
    #pragma unroll
    for (int j = 0; j < 8; j++) {
        #pragma unroll
        for (int dd = 0; dd < 2; dd++) {
            c[j][dd]     = __expf(c[j][dd] - mx0);     s0 += c[j][dd];
            c[j][dd + 2] = __expf(c[j][dd + 2] - mx1); s1 += c[j][dd + 2];
        }
    }
    s0 += __shfl_xor_sync(0xffffffffu, s0, 1);
    s0 += __shfl_xor_sync(0xffffffffu, s0, 2);
    s1 += __shfl_xor_sync(0xffffffffu, s1, 1);
    s1 += __shfl_xor_sync(0xffffffffu, s1, 2);
    const float inv0 = 1.0f / s0, inv1 = 1.0f / s1;
    #pragma unroll
    for (int j = 0; j < 8; j++) {
        c[j][0] *= inv0; c[j][1] *= inv0;
        c[j][2] *= inv1; c[j][3] *= inv1;
    }

    // ---- repack P (C-frag -> A-frag), split hi/lo ----
    uint32_t ph[4][4], pl[4][4];
    #pragma unroll
    for (int t = 0; t < 4; t++) {
        #pragma unroll
        for (int q = 0; q < 4; q++) {
            int nt = 2 * t + (q >> 1);
            int p0 = (q & 1) * 2;
            float x0 = c[nt][p0], x1 = c[nt][p0 + 1];
            float h0 = fhhi(x0), h1 = fhhi(x1);
            ph[t][q] = packh(h0, h1);
            pl[t][q] = packh(x0 - h0, x1 - h1);
        }
    }

    // ---- O = P v (2 segments) ----
    float o[4][4];
    #pragma unroll
    for (int nt = 0; nt < 4; nt++)
        #pragma unroll
        for (int q = 0; q < 4; q++) o[nt][q] = 0.f;

    #pragma unroll
    for (int t = 0; t < 4; t++) {
        #pragma unroll
        for (int nb = 0; nb < 2; nb++) {
            uint32_t off = (uint32_t)((nb * 16 + (lane & 7) + ((lane & 16) ? 8 : 0)) * 144 +
                                      (t * 16 + ((lane & 8) ? 8 : 0)) * 2);
            uint32_t bh[4];
            LDSM4(bh, uvh + off);
            #pragma unroll
            for (int n2 = 0; n2 < 2; n2++) {
                MMA16816(o[2 * nb + n2], ph[t], &bh[2 * n2]);
                MMA16816(o[2 * nb + n2], pl[t], &bh[2 * n2]);
            }
        }
    }

    // ---- epilogue: fp16 hi to g_att2 (stride 256) ----
    size_t rb0 = (size_t)(w * 64 + r0) * 256 + h * 32;
    size_t rb1 = (size_t)(w * 64 + r1) * 256 + h * 32;
    #pragma unroll
    for (int nt = 0; nt < 4; nt++) {
        int d0 = nt * 8 + (lane & 3) * 2;
        *(uint32_t*)(g_att2 + rb0 + d0) = packh(o[nt][0], o[nt][1]);
        *(uint32_t*)(g_att2 + rb1 + d0) = packh(o[nt][2], o[nt][3]);
    }
}

// ---------------------------------------------------------------------------
extern "C" void kernel_launch(void* const* d_in, const int* in_sizes, int n_in,
                              void* d_out, int out_size)
{
    const float* x     = (const float*)d_in[0];
    const float* w_qkv = (const float*)d_in[1];
    const float* b_qkv = (const float*)d_in[2];
    const float* w_out = (const float*)d_in[3];
    const float* b_out = (const float*)d_in[4];
    const float* pos   = (const float*)d_in[5];
    float* out = (float*)d_out;

    const int SMEM = 65536;
    cudaFuncSetAttribute(mma_gemm<6, 512, false>,
                         cudaFuncAttributeMaxDynamicSharedMemorySize, SMEM);
    cudaFuncSetAttribute(mma_gemm<2, 256, true>,
                         cudaFuncAttributeMaxDynamicSharedMemorySize, SMEM);

    convert_kernel<<<32768, 256>>>(x, 131072, 0);
    convert_kernel<<<192,   256>>>(w_qkv, 768, 1);
    convert_kernel<<<64,    256>>>(w_out, 256, 2);
    mma_gemm<6, 512, false><<<dim3(6, 1024), 256, SMEM>>>(b_qkv, nullptr);
    attn_kernel<<<dim3(2048, 8), 128>>>(pos);
    mma_gemm<2, 256, true><<<dim3(2, 1024), 256, SMEM>>>(b_out, out);
}

// round 9
// speedup vs baseline: 4.5975x; 1.2795x over previous
#include <cuda_runtime.h>
#include <cuda_fp16.h>
#include <math.h>
#include <stdint.h>

// ---------------------------------------------------------------------------
// ShiftedWindowAttention (B=32, 64x64, C=256, 8 heads x 32, ws=8, shift=4)
//
// Everything fp16-hi on HMMA (mma.sync, fp32 accum); error budget spent
// deliberately: every intermediate rounds to fp16 once (~2.4e-4 each,
// metric-averaged), measured headroom vs 1e-3 threshold is >2x.
// K0: x (gathered) -> fp16; w_qkv, w_out -> fp16
// K1: qkv = x @ w2^T + b  -> g_q (scale folded) / g_k / g_v   (fp16 planes)
// K2: windowed attention, tensor-core, register softmax -> g_att2 fp16
// K3: out = att2 @ w3^T + b_out, rows scattered (inverse roll), f32
// ---------------------------------------------------------------------------

#define KDIM 256
typedef __half fp16;

__device__ fp16  g_x2  [131072UL * 256];   // x gathered, fp16
__device__ fp16  g_q   [131072UL * 256];   // q scaled
__device__ fp16  g_k   [131072UL * 256];
__device__ fp16  g_v   [131072UL * 256];
__device__ fp16  g_att2[131072UL * 256];   // attention out
__device__ fp16  g_w2  [768 * 256];        // w_qkv
__device__ fp16  g_w3  [256 * 256];        // w_out

static __device__ __constant__ float SCALEF = 0.17677669529663687f;  // 32^-0.5

__device__ __forceinline__ int gather_off(int gm) {
    int w  = gm >> 6;
    int t  = gm & 63;
    int b  = w >> 6;
    int wl = w & 63;
    int r  = ((wl >> 3) << 3) + (t >> 3);
    int c  = ((wl & 7) << 3) + (t & 7);
    int sr = (r + 4) & 63;
    int sc = (c + 4) & 63;
    return (b * 4096 + sr * 64 + sc) * KDIM;
}

#define SWZ(off) ((off) ^ (((off) >> 3) & 0x70))

__device__ __forceinline__ uint32_t smem_u32(const void* p) {
    uint32_t a;
    asm("{ .reg .u64 t; cvta.to.shared.u64 t, %1; cvt.u32.u64 %0, t; }"
        : "=r"(a) : "l"(p));
    return a;
}

#define LDSM4(r, addr)                                                         \
    asm volatile("ldmatrix.sync.aligned.m8n8.x4.shared.b16 {%0,%1,%2,%3}, [%4];"\
                 : "=r"((r)[0]), "=r"((r)[1]), "=r"((r)[2]), "=r"((r)[3])      \
                 : "r"(addr))

#define MMA16816(d, a, b)                                                      \
    asm volatile("mma.sync.aligned.m16n8k16.row.col.f32.f16.f16.f32 "          \
                 "{%0,%1,%2,%3}, {%4,%5,%6,%7}, {%8,%9}, {%0,%1,%2,%3};"       \
                 : "+f"((d)[0]), "+f"((d)[1]), "+f"((d)[2]), "+f"((d)[3])      \
                 : "r"((a)[0]), "r"((a)[1]), "r"((a)[2]), "r"((a)[3]),         \
                   "r"((b)[0]), "r"((b)[1]))

__device__ __forceinline__ uint32_t packh(float lo, float hi) {
    __half2 h = __floats2half2_rn(lo, hi);
    return *(uint32_t*)&h;
}

// ---------------------------------------------------------------------------
// K0: conversion. mode 0: x (gathered) -> g_x2
//                 mode 1: w_qkv -> g_w2,  mode 2: w_out -> g_w3
// ---------------------------------------------------------------------------
__global__ void convert_kernel(const float* __restrict__ src, int nrows, int mode)
{
    int idx = blockIdx.x * blockDim.x + threadIdx.x;
    if (idx >= nrows * 64) return;
    int row = idx >> 6;
    int c   = (idx & 63) << 2;
    const float* sp = src + (mode == 0 ? gather_off(row) : row * 256) + c;
    float4 v = *(const float4*)sp;

    fp16 __align__(8) hi[4];
    hi[0] = __float2half_rn(v.x);
    hi[1] = __float2half_rn(v.y);
    hi[2] = __float2half_rn(v.z);
    hi[3] = __float2half_rn(v.w);

    fp16* dst = (mode == 0) ? g_x2 : ((mode == 1) ? g_w2 : g_w3);
    *(uint2*)(dst + (size_t)row * 256 + c) = *(uint2*)hi;
}

// ---------------------------------------------------------------------------
// mma.sync GEMM.  C[128 x 128] per CTA, 8 warps, warp tile 64x32.
// K = 256 = 4 chunks of 64 cols, 2-stage cp.async pipeline.
// !SCATTER: epilogue writes fp16 planes g_q (scaled) / g_k / g_v.
// SCATTER:  f32 output, inverse-roll row scatter.
// ---------------------------------------------------------------------------
template <int NT, bool SCATTER>
__global__ __launch_bounds__(256, 2) void mma_gemm(const float* __restrict__ bias,
                                                   float* __restrict__ Cout)
{
    extern __shared__ __align__(1024) char smem[];
    const fp16* Ag = SCATTER ? g_att2 : g_x2;
    const fp16* Bg = SCATTER ? g_w3   : g_w2;

    const int tid  = threadIdx.x;
    const int lane = tid & 31;
    const int warp = tid >> 5;
    const int m0   = blockIdx.y * 128;
    const int n0c  = blockIdx.x * 128;
    const uint32_t sbase = smem_u32(smem);

    auto stage = [&](int c, int buf) {
        int kin = c * 64;
        uint32_t ab = sbase + buf * 32768;
        uint32_t bb = ab + 16384;
        #pragma unroll
        for (int i = 0; i < 4; i++) {
            int idx = tid + i * 256;
            int r  = idx >> 3;
            int ch = idx & 7;
            uint32_t off = (uint32_t)(r * 128 + ch * 16);
            const fp16* as = Ag + (size_t)(m0 + r) * 256 + kin + ch * 8;
            const fp16* bs = Bg + (size_t)(n0c + r) * 256 + kin + ch * 8;
            asm volatile("cp.async.cg.shared.global [%0], [%1], 16;"
                         :: "r"(ab + SWZ(off)), "l"(as));
            asm volatile("cp.async.cg.shared.global [%0], [%1], 16;"
                         :: "r"(bb + SWZ(off)), "l"(bs));
        }
        asm volatile("cp.async.commit_group;");
    };

    float d[4][4][4];
    #pragma unroll
    for (int mt = 0; mt < 4; mt++)
        #pragma unroll
        for (int nt = 0; nt < 4; nt++)
            #pragma unroll
            for (int j = 0; j < 4; j++) d[mt][nt][j] = 0.f;

    const int wm0 = (warp >> 2) * 64;
    const int wn0 = (warp & 3) * 32;

    stage(0, 0);
    #pragma unroll 1
    for (int c = 0; c < 4; c++) {
        if (c < 3) {
            stage(c + 1, (c + 1) & 1);
            asm volatile("cp.async.wait_group 1;");
        } else {
            asm volatile("cp.async.wait_group 0;");
        }
        __syncthreads();

        uint32_t ab = sbase + (c & 1) * 32768;
        uint32_t bb = ab + 16384;

        #pragma unroll
        for (int ks = 0; ks < 4; ks++) {
            uint32_t a[4][4], b[4][2];
            #pragma unroll
            for (int mt = 0; mt < 4; mt++) {
                int row = wm0 + mt * 16 + (lane & 15);
                int col = ks * 16 + ((lane >> 1) & 8);
                uint32_t off = (uint32_t)(row * 128 + col * 2);
                LDSM4(a[mt], ab + SWZ(off));
            }
            #pragma unroll
            for (int np = 0; np < 2; np++) {
                int row = wn0 + np * 16 + (lane & 7) + ((lane & 16) ? 8 : 0);
                int col = ks * 16 + ((lane & 8) ? 8 : 0);
                uint32_t off = (uint32_t)(row * 128 + col * 2);
                uint32_t t[4];
                LDSM4(t, bb + SWZ(off));
                b[2 * np][0] = t[0]; b[2 * np][1] = t[1];
                b[2 * np + 1][0] = t[2]; b[2 * np + 1][1] = t[3];
            }
            #pragma unroll
            for (int mt = 0; mt < 4; mt++)
                #pragma unroll
                for (int nt = 0; nt < 4; nt++)
                    MMA16816(d[mt][nt], a[mt], b[nt]);
        }
        if (c < 3) __syncthreads();
    }

    const int cc0 = n0c + wn0 + (lane & 3) * 2;
    if (SCATTER) {
        #pragma unroll
        for (int mt = 0; mt < 4; mt++) {
            int g0 = m0 + wm0 + mt * 16 + (lane >> 2);
            size_t ob0 = (size_t)gather_off(g0);
            size_t ob1 = (size_t)gather_off(g0 + 8);
            #pragma unroll
            for (int nt = 0; nt < 4; nt++) {
                int col = cc0 + nt * 8;
                float bx = bias[col], by = bias[col + 1];
                float2 o0 = {d[mt][nt][0] + bx, d[mt][nt][1] + by};
                float2 o1 = {d[mt][nt][2] + bx, d[mt][nt][3] + by};
                *(float2*)(Cout + ob0 + col) = o0;
                *(float2*)(Cout + ob1 + col) = o1;
            }
        }
    } else {
        fp16* dst   = (n0c < 256) ? g_q : ((n0c < 512) ? g_k : g_v);
        int   cbase = (n0c < 256) ? 0   : ((n0c < 512) ? 256 : 512);
        const float scl = (n0c < 256) ? SCALEF : 1.0f;
        #pragma unroll
        for (int mt = 0; mt < 4; mt++) {
            int g0 = m0 + wm0 + mt * 16 + (lane >> 2);
            #pragma unroll
            for (int nt = 0; nt < 4; nt++) {
                int col = cc0 + nt * 8;
                float bx = bias[col], by = bias[col + 1];
                float v0 = (d[mt][nt][0] + bx) * scl, v1 = (d[mt][nt][1] + by) * scl;
                float v2 = (d[mt][nt][2] + bx) * scl, v3 = (d[mt][nt][3] + by) * scl;
                int cc = col - cbase;
                *(uint32_t*)(dst + (size_t)g0 * 256 + cc)       = packh(v0, v1);
                *(uint32_t*)(dst + (size_t)(g0 + 8) * 256 + cc) = packh(v2, v3);
            }
        }
    }
}

// ---------------------------------------------------------------------------
// K2: tensor-core windowed attention, everything single fp16.
// One block per (window, head), 4 warps, warp = 16 query rows.
// ---------------------------------------------------------------------------
__global__ __launch_bounds__(128) void attn_kernel(const float* __restrict__ pos_enc)
{
    __shared__ fp16 qh[64 * 40];
    __shared__ fp16 kh[64 * 40];
    __shared__ fp16 vh[32 * 72];               // transposed [dim][col]
    __shared__ float pe[225];
    __shared__ int   rg[64];

    const int w    = blockIdx.x;
    const int h    = blockIdx.y;
    const int tid  = threadIdx.x;
    const int lane = tid & 31;
    const int wp   = tid >> 5;

    const size_t rowbase = (size_t)(w * 64);

    for (int t = tid; t < 256; t += 128) {
        int i = t >> 2, d0 = (t & 3) * 8;
        *(uint4*)(qh + i * 40 + d0) =
            *(const uint4*)(g_q + (rowbase + i) * 256 + h * 32 + d0);
    }
    for (int t = tid; t < 256; t += 128) {
        int i = t >> 2, d0 = (t & 3) * 8;
        *(uint4*)(kh + i * 40 + d0) =
            *(const uint4*)(g_k + (rowbase + i) * 256 + h * 32 + d0);
    }
    for (int t = tid; t < 256; t += 128) {
        int i = t >> 2, d0 = (t & 3) * 8;
        fp16 tmp[8];
        *(uint4*)tmp = *(const uint4*)(g_v + (rowbase + i) * 256 + h * 32 + d0);
        #pragma unroll
        for (int e = 0; e < 8; e++) vh[(d0 + e) * 72 + i] = tmp[e];
    }
    for (int idx = tid; idx < 225; idx += 128) pe[idx] = pos_enc[h * 225 + idx];
    if (tid < 64) {
        int wl = w & 63;
        int r  = ((wl >> 3) << 3) + (tid >> 3);
        int c  = ((wl & 7) << 3) + (tid & 7);
        int rr = (r < 56) ? 0 : ((r < 60) ? 1 : 2);
        int cc = (c < 56) ? 0 : ((c < 60) ? 1 : 2);
        rg[tid] = rr * 3 + cc;
    }
    __syncthreads();

    const uint32_t uqh = smem_u32(qh);
    const uint32_t ukh = smem_u32(kh);
    const uint32_t uvh = smem_u32(vh);

    // ---- S = q k^T ----
    float c[8][4];
    #pragma unroll
    for (int j = 0; j < 8; j++)
        #pragma unroll
        for (int q = 0; q < 4; q++) c[j][q] = 0.f;

    uint32_t aq[2][4];
    #pragma unroll
    for (int ks = 0; ks < 2; ks++) {
        uint32_t off = (uint32_t)((wp * 16 + (lane & 15)) * 80 +
                                  (ks * 16 + ((lane >> 1) & 8)) * 2);
        LDSM4(aq[ks], uqh + off);
    }
    #pragma unroll
    for (int np = 0; np < 4; np++) {
        #pragma unroll
        for (int ks = 0; ks < 2; ks++) {
            uint32_t off = (uint32_t)((np * 16 + (lane & 7) + ((lane & 16) ? 8 : 0)) * 80 +
                                      (ks * 16 + ((lane & 8) ? 8 : 0)) * 2);
            uint32_t bh[4];
            LDSM4(bh, ukh + off);
            MMA16816(c[2 * np],     aq[ks], &bh[0]);
            MMA16816(c[2 * np + 1], aq[ks], &bh[2]);
        }
    }

    // ---- bias + mask + softmax on fragments ----
    const int r0 = wp * 16 + (lane >> 2);
    const int r1 = r0 + 8;
    const int yi0 = r0 >> 3, xi0 = r0 & 7, ri0 = rg[r0];
    const int yi1 = r1 >> 3, xi1 = r1 & 7, ri1 = rg[r1];
    float mx0 = -INFINITY, mx1 = -INFINITY;
    #pragma unroll
    for (int j = 0; j < 8; j++) {
        #pragma unroll
        for (int dd = 0; dd < 2; dd++) {
            int col = j * 8 + (lane & 3) * 2 + dd;
            int yj = col >> 3, xj = col & 7;
            int rc = rg[col];
            c[j][dd]     = (rc == ri0)
                ? c[j][dd]     + pe[(yi0 - yj + 7) * 15 + (xi0 - xj + 7)] : -INFINITY;
            c[j][dd + 2] = (rc == ri1)
                ? c[j][dd + 2] + pe[(yi1 - yj + 7) * 15 + (xi1 - xj + 7)] : -INFINITY;
            mx0 = fmaxf(mx0, c[j][dd]);
            mx1 = fmaxf(mx1, c[j][dd + 2]);
        }
    }
    mx0 = fmaxf(mx0, __shfl_xor_sync(0xffffffffu, mx0, 1));
    mx0 = fmaxf(mx0, __shfl_xor_sync(0xffffffffu, mx0, 2));
    mx1 = fmaxf(mx1, __shfl_xor_sync(0xffffffffu, mx1, 1));
    mx1 = fmaxf(mx1, __shfl_xor_sync(0xffffffffu, mx1, 2));
    float s0 = 0.f, s1 = 0.f;
    #pragma unroll
    for (int j = 0; j < 8; j++) {
        #pragma unroll
        for (int dd = 0; dd < 2; dd++) {
            c[j][dd]     = __expf(c[j][dd] - mx0);     s0 += c[j][dd];
            c[j][dd + 2] = __expf(c[j][dd + 2] - mx1); s1 += c[j][dd + 2];
        }
    }
    s0 += __shfl_xor_sync(0xffffffffu, s0, 1);
    s0 += __shfl_xor_sync(0xffffffffu, s0, 2);
    s1 += __shfl_xor_sync(0xffffffffu, s1, 1);
    s1 += __shfl_xor_sync(0xffffffffu, s1, 2);
    const float inv0 = 1.0f / s0, inv1 = 1.0f / s1;

    // ---- repack P (C-frag -> A-frag), single fp16 ----
    uint32_t ph[4][4];
    #pragma unroll
    for (int t = 0; t < 4; t++) {
        #pragma unroll
        for (int q = 0; q < 4; q++) {
            int nt = 2 * t + (q >> 1);
            int p0 = (q & 1) * 2;
            float iv = (q & 1) ? inv1 : inv0;   // p0=0 -> rows r0, p0=2 -> r1
            // careful: c[nt][0..1] are row r0, c[nt][2..3] are row r1
            float x0 = c[nt][p0]     * ((p0 == 0) ? inv0 : inv1);
            float x1 = c[nt][p0 + 1] * ((p0 == 0) ? inv0 : inv1);
            (void)iv;
            ph[t][q] = packh(x0, x1);
        }
    }

    // ---- O = P v ----
    float o[4][4];
    #pragma unroll
    for (int nt = 0; nt < 4; nt++)
        #pragma unroll
        for (int q = 0; q < 4; q++) o[nt][q] = 0.f;

    #pragma unroll
    for (int t = 0; t < 4; t++) {
        #pragma unroll
        for (int nb = 0; nb < 2; nb++) {
            uint32_t off = (uint32_t)((nb * 16 + (lane & 7) + ((lane & 16) ? 8 : 0)) * 144 +
                                      (t * 16 + ((lane & 8) ? 8 : 0)) * 2);
            uint32_t bh[4];
            LDSM4(bh, uvh + off);
            MMA16816(o[2 * nb],     ph[t], &bh[0]);
            MMA16816(o[2 * nb + 1], ph[t], &bh[2]);
        }
    }

    // ---- epilogue: fp16 to g_att2 ----
    size_t rb0 = (size_t)(w * 64 + r0) * 256 + h * 32;
    size_t rb1 = (size_t)(w * 64 + r1) * 256 + h * 32;
    #pragma unroll
    for (int nt = 0; nt < 4; nt++) {
        int d0 = nt * 8 + (lane & 3) * 2;
        *(uint32_t*)(g_att2 + rb0 + d0) = packh(o[nt][0], o[nt][1]);
        *(uint32_t*)(g_att2 + rb1 + d0) = packh(o[nt][2], o[nt][3]);
    }
}

// ---------------------------------------------------------------------------
extern "C" void kernel_launch(void* const* d_in, const int* in_sizes, int n_in,
                              void* d_out, int out_size)
{
    const float* x     = (const float*)d_in[0];
    const float* w_qkv = (const float*)d_in[1];
    const float* b_qkv = (const float*)d_in[2];
    const float* w_out = (const float*)d_in[3];
    const float* b_out = (const float*)d_in[4];
    const float* pos   = (const float*)d_in[5];
    float* out = (float*)d_out;

    const int SMEM = 65536;
    cudaFuncSetAttribute(mma_gemm<6, false>,
                         cudaFuncAttributeMaxDynamicSharedMemorySize, SMEM);
    cudaFuncSetAttribute(mma_gemm<2, true>,
                         cudaFuncAttributeMaxDynamicSharedMemorySize, SMEM);

    convert_kernel<<<32768, 256>>>(x, 131072, 0);
    convert_kernel<<<192,   256>>>(w_qkv, 768, 1);
    convert_kernel<<<64,    256>>>(w_out, 256, 2);
    mma_gemm<6, false><<<dim3(6, 1024), 256, SMEM>>>(b_qkv, nullptr);
    attn_kernel<<<dim3(2048, 8), 128>>>(pos);
    mma_gemm<2, true><<<dim3(2, 1024), 256, SMEM>>>(b_out, out);
}